// round 6
// baseline (speedup 1.0000x reference)
#include <cuda_runtime.h>
#include <cuda_bf16.h>
#include <cstdint>

// Problem constants: B=2, S=2048, D=1024, H=16, hd=64, FF=4096
#define BB 2
#define SS 2048
#define DD 1024
#define HH 16
#define HD 64
#define FF_DIM 4096
#define MTOK (BB*SS)          // 4096 rows

typedef __nv_bfloat16 bf16;

// ---------------------------------------------------------------------------
// Scratch (device globals; no allocation allowed)
// ---------------------------------------------------------------------------
__device__ bf16 g_qkvh[(size_t)MTOK * 3 * DD], g_qkvl[(size_t)MTOK * 3 * DD];
__device__ float g_h1pre[(size_t)MTOK * DD];
__device__ float g_h1[(size_t)MTOK * DD];
__device__ float g_h2pre[(size_t)MTOK * DD];

__device__ bf16 g_xh[(size_t)MTOK * DD],      g_xl[(size_t)MTOK * DD];
__device__ bf16 g_ah[(size_t)MTOK * DD],      g_al[(size_t)MTOK * DD];   // attn out
__device__ bf16 g_h1h[(size_t)MTOK * DD],     g_h1l[(size_t)MTOK * DD];
__device__ bf16 g_midh[(size_t)MTOK * FF_DIM], g_midl[(size_t)MTOK * FF_DIM];
__device__ bf16 g_wqh[(size_t)3 * DD * DD],   g_wql[(size_t)3 * DD * DD];
__device__ bf16 g_owh[(size_t)DD * DD],       g_owl[(size_t)DD * DD];
__device__ bf16 g_w1h[(size_t)FF_DIM * DD],   g_w1l[(size_t)FF_DIM * DD];
__device__ bf16 g_w2h[(size_t)DD * FF_DIM],   g_w2l[(size_t)DD * FF_DIM];

// ---------------------------------------------------------------------------
// MMA / ldmatrix / cp.async helpers
// ---------------------------------------------------------------------------
__device__ __forceinline__ uint32_t smem_u32(const void* p) {
    uint32_t a;
    asm("{ .reg .u64 t; cvta.to.shared.u64 t, %1; cvt.u32.u64 %0, t; }"
        : "=r"(a) : "l"(p));
    return a;
}
__device__ __forceinline__ void ldsm4(uint32_t* r, uint32_t a) {
    asm volatile("ldmatrix.sync.aligned.m8n8.x4.shared.b16 {%0,%1,%2,%3}, [%4];"
                 : "=r"(r[0]), "=r"(r[1]), "=r"(r[2]), "=r"(r[3]) : "r"(a));
}
__device__ __forceinline__ void ldsm4t(uint32_t* r, uint32_t a) {
    asm volatile("ldmatrix.sync.aligned.m8n8.x4.trans.shared.b16 {%0,%1,%2,%3}, [%4];"
                 : "=r"(r[0]), "=r"(r[1]), "=r"(r[2]), "=r"(r[3]) : "r"(a));
}
__device__ __forceinline__ void mma16816(float* c, const uint32_t* a, const uint32_t* b) {
    asm volatile(
        "mma.sync.aligned.m16n8k16.row.col.f32.bf16.bf16.f32 "
        "{%0,%1,%2,%3}, {%4,%5,%6,%7}, {%8,%9}, {%0,%1,%2,%3};"
        : "+f"(c[0]), "+f"(c[1]), "+f"(c[2]), "+f"(c[3])
        : "r"(a[0]), "r"(a[1]), "r"(a[2]), "r"(a[3]), "r"(b[0]), "r"(b[1]));
}
#define CP16(dst, src) \
    asm volatile("cp.async.cg.shared.global [%0], [%1], 16;" :: "r"(dst), "l"(src) : "memory")
#define CP_COMMIT() asm volatile("cp.async.commit_group;" ::: "memory")
#define CP_WAIT2()  asm volatile("cp.async.wait_group 2;" ::: "memory")
#define CP_WAIT1()  asm volatile("cp.async.wait_group 1;" ::: "memory")
#define CP_WAIT0()  asm volatile("cp.async.wait_group 0;" ::: "memory")
__device__ __forceinline__ void cp_wait_rem(int rem) {
    if (rem >= 2)      CP_WAIT2();
    else if (rem == 1) CP_WAIT1();
    else               CP_WAIT0();
}

// 128B-row tile (flash): row stride 128B, chunk ch swizzled by row&7.
__device__ __forceinline__ uint32_t tile_addr(uint32_t base, int row, int ch) {
    return base + (uint32_t)row * 128u + (uint32_t)((ch ^ (row & 7)) << 4);
}
// paired-row tile (gemm): [128][32] bf16 in 64 smem rows of 128B.
__device__ __forceinline__ uint32_t tile2_addr(uint32_t base, int r, int k) {
    const int s = r >> 1;
    const int c = ((r & 1) << 2) | k;
    return base + (uint32_t)s * 128u + (uint32_t)((c ^ (s & 7)) << 4);
}
__device__ __forceinline__ uint32_t pack_hi(float a, float b) {
    __nv_bfloat162 h = __halves2bfloat162(__float2bfloat16(a), __float2bfloat16(b));
    return *(uint32_t*)&h;
}
__device__ __forceinline__ uint32_t pack_lo(float a, float b) {
    bf16 ha = __float2bfloat16(a), hb = __float2bfloat16(b);
    __nv_bfloat162 l = __halves2bfloat162(__float2bfloat16(a - __bfloat162float(ha)),
                                          __float2bfloat16(b - __bfloat162float(hb)));
    return *(uint32_t*)&l;
}

// ---------------------------------------------------------------------------
// Split-bf16 tensor-core GEMM, 3-stage cp.async pipeline (2 stages in flight).
// 128x128 CTA tile, 8 warps (2Mx4N), warp tile 64x32, K-stage 32.
// Smem 96KB -> 2 CTAs/SM.
// ---------------------------------------------------------------------------
#define GEMM_SMEM (3 * 32768)   // 96KB

__global__ __launch_bounds__(256, 2) void gemm_mma(
    const bf16* __restrict__ Ah, const bf16* __restrict__ Al,
    const bf16* __restrict__ Wh, const bf16* __restrict__ Wl,
    const float* __restrict__ bias, const float* __restrict__ res,
    float* __restrict__ C, bf16* __restrict__ Chi, bf16* __restrict__ Clo,
    float* __restrict__ kd, float* __restrict__ vd,
    int M, int N, int K, int relu)
{
    extern __shared__ char dsm[];
    const uint32_t sb = smem_u32(dsm);

    const int tid = threadIdx.x;
    const int lid = tid & 31;
    const int wid = tid >> 5;
    const int wm = wid & 1;
    const int wn = wid >> 1;
    const int bm = blockIdx.y * 128, bn = blockIdx.x * 128;

    const bf16* gs[4] = { Ah + (size_t)bm * K, Al + (size_t)bm * K,
                          Wh + (size_t)bn * K, Wl + (size_t)bn * K };

    float acc[4][4][4];
#pragma unroll
    for (int i = 0; i < 4; ++i)
#pragma unroll
        for (int j = 0; j < 4; ++j)
#pragma unroll
            for (int k = 0; k < 4; ++k) acc[i][j][k] = 0.f;

    const int NC = K >> 5;

    auto load_stage = [&](int stage, int kk) {
        const uint32_t stb = sb + (uint32_t)stage * 32768u;
        const int r  = tid >> 1;
        const int k0 = (tid & 1) * 2;
#pragma unroll
        for (int t4 = 0; t4 < 4; ++t4) {
            const uint32_t tb = stb + (uint32_t)t4 * 8192u;
            const bf16* g = gs[t4] + kk + (size_t)r * K;
#pragma unroll
            for (int j = 0; j < 2; ++j)
                CP16(tile2_addr(tb, r, k0 + j), (const char*)(g + (k0 + j) * 8));
        }
        CP_COMMIT();
    };

    load_stage(0, 0);
    load_stage(1, 32);

    const int arow = lid & 15;
    const int achd = lid >> 4;

    for (int c = 0; c < NC; ++c) {
        if (c + 2 < NC) load_stage((c + 2) % 3, (c + 2) << 5);
        cp_wait_rem(NC - 1 - c);
        __syncthreads();

        const uint32_t stb = sb + (uint32_t)(c % 3) * 32768u;

#pragma unroll
        for (int ks = 0; ks < 2; ++ks) {
            const int chk = ks * 2 + achd;
            uint32_t ah[4][4], al[4][4];
#pragma unroll
            for (int mt = 0; mt < 4; ++mt) {
                const int r = wm * 64 + mt * 16 + arow;
                ldsm4(ah[mt], tile2_addr(stb, r, chk));
                ldsm4(al[mt], tile2_addr(stb + 8192u, r, chk));
            }
            uint32_t bh[4][2], bl[4][2];
#pragma unroll
            for (int ntp = 0; ntp < 2; ++ntp) {
                const int r = wn * 32 + ntp * 16 + arow;
                uint32_t t[4], u[4];
                ldsm4(t, tile2_addr(stb + 16384u, r, chk));
                ldsm4(u, tile2_addr(stb + 24576u, r, chk));
                bh[2 * ntp][0] = t[0]; bh[2 * ntp][1] = t[2];
                bh[2 * ntp + 1][0] = t[1]; bh[2 * ntp + 1][1] = t[3];
                bl[2 * ntp][0] = u[0]; bl[2 * ntp][1] = u[2];
                bl[2 * ntp + 1][0] = u[1]; bl[2 * ntp + 1][1] = u[3];
            }
#pragma unroll
            for (int mt = 0; mt < 4; ++mt)
#pragma unroll
                for (int nt = 0; nt < 4; ++nt)
                    mma16816(acc[mt][nt], ah[mt], bh[nt]);
#pragma unroll
            for (int mt = 0; mt < 4; ++mt)
#pragma unroll
                for (int nt = 0; nt < 4; ++nt)
                    mma16816(acc[mt][nt], ah[mt], bl[nt]);
#pragma unroll
            for (int mt = 0; mt < 4; ++mt)
#pragma unroll
                for (int nt = 0; nt < 4; ++nt)
                    mma16816(acc[mt][nt], al[mt], bh[nt]);
        }
        __syncthreads();
    }

    const int l4 = lid >> 2;
    const int l2 = (lid & 3) * 2;
#pragma unroll
    for (int mt = 0; mt < 4; ++mt) {
#pragma unroll
        for (int nt = 0; nt < 4; ++nt) {
            const int col = bn + wn * 32 + nt * 8 + l2;
#pragma unroll
            for (int half = 0; half < 2; ++half) {
                const int row = bm + wm * 64 + mt * 16 + l4 + half * 8;
                float v0 = acc[mt][nt][2 * half + 0];
                float v1 = acc[mt][nt][2 * half + 1];
                v0 += bias[col]; v1 += bias[col + 1];
                const size_t o = (size_t)row * N + col;
                if (res) { v0 += res[o]; v1 += res[o + 1]; }
                if (relu) { v0 = fmaxf(v0, 0.f); v1 = fmaxf(v1, 0.f); }
                if (C) *(float2*)(C + o) = make_float2(v0, v1);
                if (kd) {
                    if (col >= 2048)
                        *(float2*)(vd + (size_t)row * DD + col - 2048) = make_float2(v0, v1);
                    else if (col >= 1024)
                        *(float2*)(kd + (size_t)row * DD + col - 1024) = make_float2(v0, v1);
                }
                if (Chi) {
                    *(uint32_t*)(Chi + o) = pack_hi(v0, v1);
                    *(uint32_t*)(Clo + o) = pack_lo(v0, v1);
                }
            }
        }
    }
}

// ---------------------------------------------------------------------------
// fp32 -> (hi, lo) bf16 split
// ---------------------------------------------------------------------------
__global__ __launch_bounds__(256) void cvt_hilo_k(
    const float4* __restrict__ in, uint32_t* __restrict__ hi,
    uint32_t* __restrict__ lo, int n4)
{
    int i = blockIdx.x * blockDim.x + threadIdx.x;
    if (i >= n4) return;
    float4 v = in[i];
    hi[2 * i]     = pack_hi(v.x, v.y);
    hi[2 * i + 1] = pack_hi(v.z, v.w);
    lo[2 * i]     = pack_lo(v.x, v.y);
    lo[2 * i + 1] = pack_lo(v.z, v.w);
}

// ---------------------------------------------------------------------------
// Tensor-core flash attention, causal, split-bf16 (3-term), online softmax.
// CTA = 128 queries of one (b,h); 3-buffer KV pipeline (2 blocks in flight).
// ---------------------------------------------------------------------------
#define FA_SMEM (32768 + 3 * 32768)   // 128KB

__global__ __launch_bounds__(256) void flash_mma_k(
    const bf16* __restrict__ qh, const bf16* __restrict__ ql,
    bf16* __restrict__ oh, bf16* __restrict__ ol)
{
    extern __shared__ char dsm[];
    const uint32_t sb = smem_u32(dsm);
    const uint32_t Qh = sb, Ql = sb + 16384u;

    const int tid = threadIdx.x;
    const int lid = tid & 31;
    const int w   = tid >> 5;
    const int q0  = blockIdx.x * 128;
    const int b   = blockIdx.y >> 4;
    const int h   = blockIdx.y & 15;
    const size_t grow = (size_t)(b * SS);

    auto load_q = [&]() {
        const int row = tid >> 1;
        const int cb  = (tid & 1) * 4;
        const size_t src = (grow + q0 + row) * 3072 + h * HD;
#pragma unroll
        for (int j = 0; j < 4; ++j) {
            const int ch = cb + j;
            CP16(tile_addr(Qh, row, ch), (const char*)(qh + src + ch * 8));
            CP16(tile_addr(Ql, row, ch), (const char*)(ql + src + ch * 8));
        }
    };
    auto load_kv = [&](int buf, int k0) {
        const uint32_t bbase = sb + 32768u + (uint32_t)buf * 32768u;
        const int row = tid >> 2;
        const int cb  = (tid & 3) * 2;
        const size_t srcK = (grow + k0 + row) * 3072 + 1024 + h * HD;
        const size_t srcV = srcK + 1024;
#pragma unroll
        for (int j = 0; j < 2; ++j) {
            const int ch = cb + j;
            const uint32_t off = tile_addr(0, row, ch);
            CP16(bbase + off,           (const char*)(qh + srcK + ch * 8));
            CP16(bbase + 8192u + off,   (const char*)(ql + srcK + ch * 8));
            CP16(bbase + 16384u + off,  (const char*)(qh + srcV + ch * 8));
            CP16(bbase + 24576u + off,  (const char*)(ql + srcV + ch * 8));
        }
    };

    const int nblk = q0 / 64 + 2;

    load_q();
    load_kv(0, 0);
    CP_COMMIT();
    load_kv(1, 64);      // nblk >= 2 always
    CP_COMMIT();

    const int arow = lid & 15;
    const int achd = lid >> 4;

    uint32_t qfh[4][4], qfl[4][4];
    float of[8][4];
#pragma unroll
    for (int i = 0; i < 8; ++i)
#pragma unroll
        for (int j = 0; j < 4; ++j) of[i][j] = 0.f;
    float m0 = -1e30f, m1 = -1e30f, l0 = 0.f, l1 = 0.f;

    const int row_lo = lid >> 2;

    for (int c = 0; c < nblk; ++c) {
        if (c + 2 < nblk) { load_kv((c + 2) % 3, (c + 2) * 64); CP_COMMIT(); }
        cp_wait_rem(nblk - 1 - c);
        __syncthreads();

        if (c == 0) {
#pragma unroll
            for (int ks = 0; ks < 4; ++ks) {
                const uint32_t ad = tile_addr(Qh, w * 16 + arow, ks * 2 + achd);
                ldsm4(qfh[ks], ad);
                ldsm4(qfl[ks], ad + 16384u);
            }
        }

        const uint32_t kb = sb + 32768u + (uint32_t)(c % 3) * 32768u;
        const int k0 = c * 64;

        float sf[8][4];
#pragma unroll
        for (int i = 0; i < 8; ++i)
#pragma unroll
            for (int j = 0; j < 4; ++j) sf[i][j] = 0.f;

#pragma unroll
        for (int ks = 0; ks < 4; ++ks) {
            uint32_t bh[8][2], bl[8][2];
#pragma unroll
            for (int ntp = 0; ntp < 4; ++ntp) {
                const uint32_t bd = tile_addr(kb, ntp * 16 + arow, ks * 2 + achd);
                uint32_t t[4], u[4];
                ldsm4(t, bd);
                ldsm4(u, bd + 8192u);
                bh[2 * ntp][0] = t[0]; bh[2 * ntp][1] = t[2];
                bh[2 * ntp + 1][0] = t[1]; bh[2 * ntp + 1][1] = t[3];
                bl[2 * ntp][0] = u[0]; bl[2 * ntp][1] = u[2];
                bl[2 * ntp + 1][0] = u[1]; bl[2 * ntp + 1][1] = u[3];
            }
#pragma unroll
            for (int nt = 0; nt < 8; ++nt) mma16816(sf[nt], qfh[ks], bh[nt]);
#pragma unroll
            for (int nt = 0; nt < 8; ++nt) mma16816(sf[nt], qfh[ks], bl[nt]);
#pragma unroll
            for (int nt = 0; nt < 8; ++nt) mma16816(sf[nt], qfl[ks], bh[nt]);
        }

        const int grow0 = q0 + w * 16 + row_lo;
        const int grow1 = grow0 + 8;
        const bool need_mask = (k0 + 63 > q0 + w * 16);
#pragma unroll
        for (int nt = 0; nt < 8; ++nt) {
            const int col = k0 + nt * 8 + 2 * (lid & 3);
#pragma unroll
            for (int j = 0; j < 4; ++j) sf[nt][j] *= 0.125f;
            if (need_mask) {
                if (col     > grow0) sf[nt][0] = -1e30f;
                if (col + 1 > grow0) sf[nt][1] = -1e30f;
                if (col     > grow1) sf[nt][2] = -1e30f;
                if (col + 1 > grow1) sf[nt][3] = -1e30f;
            }
        }

        float tm0 = -1e30f, tm1 = -1e30f;
#pragma unroll
        for (int nt = 0; nt < 8; ++nt) {
            tm0 = fmaxf(tm0, fmaxf(sf[nt][0], sf[nt][1]));
            tm1 = fmaxf(tm1, fmaxf(sf[nt][2], sf[nt][3]));
        }
        tm0 = fmaxf(tm0, __shfl_xor_sync(0xffffffffu, tm0, 1));
        tm0 = fmaxf(tm0, __shfl_xor_sync(0xffffffffu, tm0, 2));
        tm1 = fmaxf(tm1, __shfl_xor_sync(0xffffffffu, tm1, 1));
        tm1 = fmaxf(tm1, __shfl_xor_sync(0xffffffffu, tm1, 2));

        const float mn0 = fmaxf(m0, tm0), mn1 = fmaxf(m1, tm1);
        const float cr0 = __expf(m0 - mn0), cr1 = __expf(m1 - mn1);
        m0 = mn0; m1 = mn1;

        float ps0 = 0.f, ps1 = 0.f;
#pragma unroll
        for (int nt = 0; nt < 8; ++nt) {
            sf[nt][0] = __expf(sf[nt][0] - mn0);
            sf[nt][1] = __expf(sf[nt][1] - mn0);
            sf[nt][2] = __expf(sf[nt][2] - mn1);
            sf[nt][3] = __expf(sf[nt][3] - mn1);
            ps0 += sf[nt][0] + sf[nt][1];
            ps1 += sf[nt][2] + sf[nt][3];
        }
        ps0 += __shfl_xor_sync(0xffffffffu, ps0, 1);
        ps0 += __shfl_xor_sync(0xffffffffu, ps0, 2);
        ps1 += __shfl_xor_sync(0xffffffffu, ps1, 1);
        ps1 += __shfl_xor_sync(0xffffffffu, ps1, 2);
        l0 = l0 * cr0 + ps0;
        l1 = l1 * cr1 + ps1;
#pragma unroll
        for (int nt = 0; nt < 8; ++nt) {
            of[nt][0] *= cr0; of[nt][1] *= cr0;
            of[nt][2] *= cr1; of[nt][3] *= cr1;
        }

        uint32_t pah[4][4], pal[4][4];
#pragma unroll
        for (int kk = 0; kk < 4; ++kk) {
            pah[kk][0] = pack_hi(sf[2 * kk][0], sf[2 * kk][1]);
            pah[kk][1] = pack_hi(sf[2 * kk][2], sf[2 * kk][3]);
            pah[kk][2] = pack_hi(sf[2 * kk + 1][0], sf[2 * kk + 1][1]);
            pah[kk][3] = pack_hi(sf[2 * kk + 1][2], sf[2 * kk + 1][3]);
            pal[kk][0] = pack_lo(sf[2 * kk][0], sf[2 * kk][1]);
            pal[kk][1] = pack_lo(sf[2 * kk][2], sf[2 * kk][3]);
            pal[kk][2] = pack_lo(sf[2 * kk + 1][0], sf[2 * kk + 1][1]);
            pal[kk][3] = pack_lo(sf[2 * kk + 1][2], sf[2 * kk + 1][3]);
        }

        const uint32_t vb = kb + 16384u;
#pragma unroll
        for (int ks = 0; ks < 4; ++ks) {
            uint32_t vh[8][2], vl[8][2];
#pragma unroll
            for (int ntp = 0; ntp < 4; ++ntp) {
                const int krow = ks * 16 + arow;
                const uint32_t vd2 = tile_addr(vb, krow, ntp * 2 + achd);
                uint32_t t[4], u[4];
                ldsm4t(t, vd2);
                ldsm4t(u, vd2 + 8192u);
                vh[2 * ntp][0] = t[0]; vh[2 * ntp][1] = t[1];
                vh[2 * ntp + 1][0] = t[2]; vh[2 * ntp + 1][1] = t[3];
                vl[2 * ntp][0] = u[0]; vl[2 * ntp][1] = u[1];
                vl[2 * ntp + 1][0] = u[2]; vl[2 * ntp + 1][1] = u[3];
            }
#pragma unroll
            for (int nt = 0; nt < 8; ++nt) mma16816(of[nt], pah[ks], vh[nt]);
#pragma unroll
            for (int nt = 0; nt < 8; ++nt) mma16816(of[nt], pah[ks], vl[nt]);
#pragma unroll
            for (int nt = 0; nt < 8; ++nt) mma16816(of[nt], pal[ks], vh[nt]);
        }
        __syncthreads();
    }

    const float iv0 = 1.0f / l0, iv1 = 1.0f / l1;
    const size_t r0 = (grow + q0 + w * 16 + row_lo) * DD + h * HD;
    const size_t r1 = r0 + 8 * DD;
#pragma unroll
    for (int nt = 0; nt < 8; ++nt) {
        const int cofs = nt * 8 + 2 * (lid & 3);
        float v0 = of[nt][0] * iv0, v1 = of[nt][1] * iv0;
        float v2 = of[nt][2] * iv1, v3 = of[nt][3] * iv1;
        *(uint32_t*)(oh + r0 + cofs) = pack_hi(v0, v1);
        *(uint32_t*)(ol + r0 + cofs) = pack_lo(v0, v1);
        *(uint32_t*)(oh + r1 + cofs) = pack_hi(v2, v3);
        *(uint32_t*)(ol + r1 + cofs) = pack_lo(v2, v3);
    }
}

// ---------------------------------------------------------------------------
// LayerNorm over D=1024, optional fused bf16 hi/lo output
// ---------------------------------------------------------------------------
__global__ __launch_bounds__(256) void layernorm_k(
    const float* __restrict__ in, const float* __restrict__ w,
    const float* __restrict__ b, float* __restrict__ out,
    bf16* __restrict__ ohi, bf16* __restrict__ olo)
{
    __shared__ float red[8];
    __shared__ float bval;
    const int tid = threadIdx.x;
    const size_t base = (size_t)blockIdx.x * DD;

    float4 v = ((const float4*)(in + base))[tid];
    float s = v.x + v.y + v.z + v.w;
#pragma unroll
    for (int off = 16; off; off >>= 1) s += __shfl_xor_sync(0xffffffffu, s, off);
    if ((tid & 31) == 0) red[tid >> 5] = s;
    __syncthreads();
    if (tid == 0) {
        float t = 0.f;
#pragma unroll
        for (int i = 0; i < 8; ++i) t += red[i];
        bval = t * (1.0f / DD);
    }
    __syncthreads();
    const float mu = bval;
    __syncthreads();

    float dx = v.x - mu, dy = v.y - mu, dz = v.z - mu, dw = v.w - mu;
    float q = dx * dx + dy * dy + dz * dz + dw * dw;
#pragma unroll
    for (int off = 16; off; off >>= 1) q += __shfl_xor_sync(0xffffffffu, q, off);
    if ((tid & 31) == 0) red[tid >> 5] = q;
    __syncthreads();
    if (tid == 0) {
        float t = 0.f;
#pragma unroll
        for (int i = 0; i < 8; ++i) t += red[i];
        bval = t * (1.0f / DD);
    }
    __syncthreads();
    const float inv = rsqrtf(bval + 1e-5f);

    float4 w4 = ((const float4*)w)[tid];
    float4 b4 = ((const float4*)b)[tid];
    float4 r = make_float4(dx * inv * w4.x + b4.x,
                           dy * inv * w4.y + b4.y,
                           dz * inv * w4.z + b4.z,
                           dw * inv * w4.w + b4.w);
    ((float4*)(out + base))[tid] = r;
    if (ohi) {
        *(uint32_t*)(ohi + base + 4 * tid)     = pack_hi(r.x, r.y);
        *(uint32_t*)(ohi + base + 4 * tid + 2) = pack_hi(r.z, r.w);
        *(uint32_t*)(olo + base + 4 * tid)     = pack_lo(r.x, r.y);
        *(uint32_t*)(olo + base + 4 * tid + 2) = pack_lo(r.z, r.w);
    }
}

// ---------------------------------------------------------------------------
// Launch
// ---------------------------------------------------------------------------
static inline void cvt(const float* in, bf16* hi, bf16* lo, size_t n) {
    int n4 = (int)(n / 4);
    cvt_hilo_k<<<(n4 + 255) / 256, 256>>>((const float4*)in,
                                          (uint32_t*)hi, (uint32_t*)lo, n4);
}

extern "C" void kernel_launch(void* const* d_in, const int* in_sizes, int n_in,
                              void* d_out, int out_size)
{
    const float* x     = (const float*)d_in[0];
    const float* qkv_w = (const float*)d_in[1];
    const float* qkv_b = (const float*)d_in[2];
    const float* out_w = (const float*)d_in[3];
    const float* out_b = (const float*)d_in[4];
    const float* w1    = (const float*)d_in[5];
    const float* b1    = (const float*)d_in[6];
    const float* w2    = (const float*)d_in[7];
    const float* b2    = (const float*)d_in[8];
    const float* ln1w  = (const float*)d_in[9];
    const float* ln1b  = (const float*)d_in[10];
    const float* ln2w  = (const float*)d_in[11];
    const float* ln2b  = (const float*)d_in[12];

    float* outp = (float*)d_out;
    float* kdst = outp + (size_t)MTOK * DD;
    float* vdst = outp + (size_t)2 * MTOK * DD;

    float *h1pre, *h1, *h2pre;
    bf16 *qkvh, *qkvl, *xh, *xl, *ah, *al, *h1h, *h1l, *midh, *midl;
    bf16 *wqh, *wql, *owh, *owl, *w1h, *w1l, *w2h, *w2l;
    cudaGetSymbolAddress((void**)&qkvh,  g_qkvh); cudaGetSymbolAddress((void**)&qkvl, g_qkvl);
    cudaGetSymbolAddress((void**)&h1pre, g_h1pre);
    cudaGetSymbolAddress((void**)&h1,    g_h1);
    cudaGetSymbolAddress((void**)&h2pre, g_h2pre);
    cudaGetSymbolAddress((void**)&xh,    g_xh);   cudaGetSymbolAddress((void**)&xl, g_xl);
    cudaGetSymbolAddress((void**)&ah,    g_ah);   cudaGetSymbolAddress((void**)&al, g_al);
    cudaGetSymbolAddress((void**)&h1h,   g_h1h);  cudaGetSymbolAddress((void**)&h1l, g_h1l);
    cudaGetSymbolAddress((void**)&midh,  g_midh); cudaGetSymbolAddress((void**)&midl, g_midl);
    cudaGetSymbolAddress((void**)&wqh,   g_wqh);  cudaGetSymbolAddress((void**)&wql, g_wql);
    cudaGetSymbolAddress((void**)&owh,   g_owh);  cudaGetSymbolAddress((void**)&owl, g_owl);
    cudaGetSymbolAddress((void**)&w1h,   g_w1h);  cudaGetSymbolAddress((void**)&w1l, g_w1l);
    cudaGetSymbolAddress((void**)&w2h,   g_w2h);  cudaGetSymbolAddress((void**)&w2l, g_w2l);

    cudaFuncSetAttribute(gemm_mma,
                         cudaFuncAttributeMaxDynamicSharedMemorySize, GEMM_SMEM);
    cudaFuncSetAttribute(flash_mma_k,
                         cudaFuncAttributeMaxDynamicSharedMemorySize, FA_SMEM);

    // 0) split weights + x into bf16 hi/lo
    cvt(qkv_w, wqh, wql, (size_t)3 * DD * DD);
    cvt(out_w, owh, owl, (size_t)DD * DD);
    cvt(w1,    w1h, w1l, (size_t)FF_DIM * DD);
    cvt(w2,    w2h, w2l, (size_t)DD * FF_DIM);
    cvt(x,     xh,  xl,  (size_t)MTOK * DD);

    // 1) QKV projection -> qkv hi/lo bf16; k/v fp32 slices straight to d_out
    gemm_mma<<<dim3(3072 / 128, MTOK / 128), 256, GEMM_SMEM>>>(
        xh, xl, wqh, wql, qkv_b, nullptr, nullptr, qkvh, qkvl, kdst, vdst,
        MTOK, 3 * DD, DD, 0);
    // 2) tensor-core flash attention -> attn hi/lo bf16
    flash_mma_k<<<dim3(SS / 128, BB * HH), 256, FA_SMEM>>>(qkvh, qkvl, ah, al);
    // 3) out projection + residual x -> h1pre
    gemm_mma<<<dim3(DD / 128, MTOK / 128), 256, GEMM_SMEM>>>(
        ah, al, owh, owl, out_b, x, h1pre, nullptr, nullptr, nullptr, nullptr,
        MTOK, DD, DD, 0);
    // 4) LN1 -> h1 fp32 + hi/lo
    layernorm_k<<<MTOK, 256>>>(h1pre, ln1w, ln1b, h1, h1h, h1l);
    // 5) MLP up + ReLU -> mid hi/lo only
    gemm_mma<<<dim3(FF_DIM / 128, MTOK / 128), 256, GEMM_SMEM>>>(
        h1h, h1l, w1h, w1l, b1, nullptr, nullptr, midh, midl, nullptr, nullptr,
        MTOK, FF_DIM, DD, 1);
    // 6) MLP down + residual h1 -> h2pre
    gemm_mma<<<dim3(DD / 128, MTOK / 128), 256, GEMM_SMEM>>>(
        midh, midl, w2h, w2l, b2, h1, h2pre, nullptr, nullptr, nullptr, nullptr,
        MTOK, DD, FF_DIM, 0);
    // 7) LN2 -> out
    layernorm_k<<<MTOK, 256>>>(h2pre, ln2w, ln2b, outp, nullptr, nullptr);
}

// round 7
// speedup vs baseline: 1.0337x; 1.0337x over previous
#include <cuda_runtime.h>
#include <cuda_bf16.h>
#include <cstdint>

// Problem constants: B=2, S=2048, D=1024, H=16, hd=64, FF=4096
#define BB 2
#define SS 2048
#define DD 1024
#define HH 16
#define HD 64
#define FF_DIM 4096
#define MTOK (BB*SS)          // 4096 rows

typedef __nv_bfloat16 bf16;

// ---------------------------------------------------------------------------
// Scratch (device globals; no allocation allowed)
// ---------------------------------------------------------------------------
__device__ bf16 g_qkvh[(size_t)MTOK * 3 * DD], g_qkvl[(size_t)MTOK * 3 * DD];
__device__ float g_h1pre[(size_t)MTOK * DD];
__device__ float g_h1[(size_t)MTOK * DD];
__device__ float g_h2pre[(size_t)MTOK * DD];

__device__ bf16 g_xh[(size_t)MTOK * DD],      g_xl[(size_t)MTOK * DD];
__device__ bf16 g_ah[(size_t)MTOK * DD],      g_al[(size_t)MTOK * DD];   // attn out
__device__ bf16 g_h1h[(size_t)MTOK * DD],     g_h1l[(size_t)MTOK * DD];
__device__ bf16 g_midh[(size_t)MTOK * FF_DIM], g_midl[(size_t)MTOK * FF_DIM];
__device__ bf16 g_wqh[(size_t)3 * DD * DD],   g_wql[(size_t)3 * DD * DD];
__device__ bf16 g_owh[(size_t)DD * DD],       g_owl[(size_t)DD * DD];
__device__ bf16 g_w1h[(size_t)FF_DIM * DD],   g_w1l[(size_t)FF_DIM * DD];
__device__ bf16 g_w2h[(size_t)DD * FF_DIM],   g_w2l[(size_t)DD * FF_DIM];

// ---------------------------------------------------------------------------
// MMA / ldmatrix / cp.async helpers
// ---------------------------------------------------------------------------
__device__ __forceinline__ uint32_t smem_u32(const void* p) {
    uint32_t a;
    asm("{ .reg .u64 t; cvta.to.shared.u64 t, %1; cvt.u32.u64 %0, t; }"
        : "=r"(a) : "l"(p));
    return a;
}
__device__ __forceinline__ void ldsm4(uint32_t* r, uint32_t a) {
    asm volatile("ldmatrix.sync.aligned.m8n8.x4.shared.b16 {%0,%1,%2,%3}, [%4];"
                 : "=r"(r[0]), "=r"(r[1]), "=r"(r[2]), "=r"(r[3]) : "r"(a));
}
__device__ __forceinline__ void ldsm4t(uint32_t* r, uint32_t a) {
    asm volatile("ldmatrix.sync.aligned.m8n8.x4.trans.shared.b16 {%0,%1,%2,%3}, [%4];"
                 : "=r"(r[0]), "=r"(r[1]), "=r"(r[2]), "=r"(r[3]) : "r"(a));
}
__device__ __forceinline__ void mma16816(float* c, const uint32_t* a, const uint32_t* b) {
    asm volatile(
        "mma.sync.aligned.m16n8k16.row.col.f32.bf16.bf16.f32 "
        "{%0,%1,%2,%3}, {%4,%5,%6,%7}, {%8,%9}, {%0,%1,%2,%3};"
        : "+f"(c[0]), "+f"(c[1]), "+f"(c[2]), "+f"(c[3])
        : "r"(a[0]), "r"(a[1]), "r"(a[2]), "r"(a[3]), "r"(b[0]), "r"(b[1]));
}
#define CP16(dst, src) \
    asm volatile("cp.async.cg.shared.global [%0], [%1], 16;" :: "r"(dst), "l"(src) : "memory")
#define CP_COMMIT() asm volatile("cp.async.commit_group;" ::: "memory")
#define CP_WAIT1()  asm volatile("cp.async.wait_group 1;" ::: "memory")
#define CP_WAIT0()  asm volatile("cp.async.wait_group 0;" ::: "memory")

// 128B-row tile (flash): row stride 128B, chunk ch swizzled by row&7.
__device__ __forceinline__ uint32_t tile_addr(uint32_t base, int row, int ch) {
    return base + (uint32_t)row * 128u + (uint32_t)((ch ^ (row & 7)) << 4);
}
// paired-row tile (gemm): [128][32] bf16 in 64 smem rows of 128B.
__device__ __forceinline__ uint32_t tile2_addr(uint32_t base, int r, int k) {
    const int s = r >> 1;
    const int c = ((r & 1) << 2) | k;
    return base + (uint32_t)s * 128u + (uint32_t)((c ^ (s & 7)) << 4);
}
__device__ __forceinline__ uint32_t pack_hi(float a, float b) {
    __nv_bfloat162 h = __halves2bfloat162(__float2bfloat16(a), __float2bfloat16(b));
    return *(uint32_t*)&h;
}
__device__ __forceinline__ uint32_t pack_lo(float a, float b) {
    bf16 ha = __float2bfloat16(a), hb = __float2bfloat16(b);
    __nv_bfloat162 l = __halves2bfloat162(__float2bfloat16(a - __bfloat162float(ha)),
                                          __float2bfloat16(b - __bfloat162float(hb)));
    return *(uint32_t*)&l;
}

// ---------------------------------------------------------------------------
// Split-bf16 tensor-core GEMM, 3-buffer cp.async pipeline, ONE sync per stage.
// Per stage c: wait(group c) -> sync -> issue load(c+2) -> compute(c).
// Buffers (c)%3 read, (c+1)%3 in flight, (c+2)%3 written: disjoint.
// 128x128 CTA tile, 8 warps (2Mx4N), warp tile 64x32, K-stage 32.
// Smem 96KB -> 2 CTAs/SM.
// ---------------------------------------------------------------------------
#define GEMM_SMEM (3 * 32768)   // 96KB

__global__ __launch_bounds__(256, 2) void gemm_mma(
    const bf16* __restrict__ Ah, const bf16* __restrict__ Al,
    const bf16* __restrict__ Wh, const bf16* __restrict__ Wl,
    const float* __restrict__ bias, const float* __restrict__ res,
    float* __restrict__ C, bf16* __restrict__ Chi, bf16* __restrict__ Clo,
    float* __restrict__ kd, float* __restrict__ vd,
    int M, int N, int K, int relu)
{
    extern __shared__ char dsm[];
    const uint32_t sb = smem_u32(dsm);

    const int tid = threadIdx.x;
    const int lid = tid & 31;
    const int wid = tid >> 5;
    const int wm = wid & 1;
    const int wn = wid >> 1;
    const int bm = blockIdx.y * 128, bn = blockIdx.x * 128;

    const bf16* gs[4] = { Ah + (size_t)bm * K, Al + (size_t)bm * K,
                          Wh + (size_t)bn * K, Wl + (size_t)bn * K };

    float acc[4][4][4];
#pragma unroll
    for (int i = 0; i < 4; ++i)
#pragma unroll
        for (int j = 0; j < 4; ++j)
#pragma unroll
            for (int k = 0; k < 4; ++k) acc[i][j][k] = 0.f;

    const int NC = K >> 5;

    auto load_stage = [&](int stage, int kk) {
        const uint32_t stb = sb + (uint32_t)stage * 32768u;
        const int r  = tid >> 1;
        const int k0 = (tid & 1) * 2;
#pragma unroll
        for (int t4 = 0; t4 < 4; ++t4) {
            const uint32_t tb = stb + (uint32_t)t4 * 8192u;
            const bf16* g = gs[t4] + kk + (size_t)r * K;
#pragma unroll
            for (int j = 0; j < 2; ++j)
                CP16(tile2_addr(tb, r, k0 + j), (const char*)(g + (k0 + j) * 8));
        }
        CP_COMMIT();
    };

    load_stage(0, 0);
    load_stage(1, 32);

    const int arow = lid & 15;
    const int achd = lid >> 4;

    for (int c = 0; c < NC; ++c) {
        if (c < NC - 1) CP_WAIT1(); else CP_WAIT0();
        __syncthreads();
        if (c + 2 < NC) load_stage((c + 2) % 3, (c + 2) << 5);

        const uint32_t stb = sb + (uint32_t)(c % 3) * 32768u;

#pragma unroll
        for (int ks = 0; ks < 2; ++ks) {
            const int chk = ks * 2 + achd;
            uint32_t ah[4][4], al[4][4];
#pragma unroll
            for (int mt = 0; mt < 4; ++mt) {
                const int r = wm * 64 + mt * 16 + arow;
                ldsm4(ah[mt], tile2_addr(stb, r, chk));
                ldsm4(al[mt], tile2_addr(stb + 8192u, r, chk));
            }
            uint32_t bh[4][2], bl[4][2];
#pragma unroll
            for (int ntp = 0; ntp < 2; ++ntp) {
                const int r = wn * 32 + ntp * 16 + arow;
                uint32_t t[4], u[4];
                ldsm4(t, tile2_addr(stb + 16384u, r, chk));
                ldsm4(u, tile2_addr(stb + 24576u, r, chk));
                bh[2 * ntp][0] = t[0]; bh[2 * ntp][1] = t[2];
                bh[2 * ntp + 1][0] = t[1]; bh[2 * ntp + 1][1] = t[3];
                bl[2 * ntp][0] = u[0]; bl[2 * ntp][1] = u[2];
                bl[2 * ntp + 1][0] = u[1]; bl[2 * ntp + 1][1] = u[3];
            }
#pragma unroll
            for (int mt = 0; mt < 4; ++mt)
#pragma unroll
                for (int nt = 0; nt < 4; ++nt)
                    mma16816(acc[mt][nt], ah[mt], bh[nt]);
#pragma unroll
            for (int mt = 0; mt < 4; ++mt)
#pragma unroll
                for (int nt = 0; nt < 4; ++nt)
                    mma16816(acc[mt][nt], ah[mt], bl[nt]);
#pragma unroll
            for (int mt = 0; mt < 4; ++mt)
#pragma unroll
                for (int nt = 0; nt < 4; ++nt)
                    mma16816(acc[mt][nt], al[mt], bh[nt]);
        }
    }

    const int l4 = lid >> 2;
    const int l2 = (lid & 3) * 2;
#pragma unroll
    for (int mt = 0; mt < 4; ++mt) {
#pragma unroll
        for (int nt = 0; nt < 4; ++nt) {
            const int col = bn + wn * 32 + nt * 8 + l2;
#pragma unroll
            for (int half = 0; half < 2; ++half) {
                const int row = bm + wm * 64 + mt * 16 + l4 + half * 8;
                float v0 = acc[mt][nt][2 * half + 0];
                float v1 = acc[mt][nt][2 * half + 1];
                v0 += bias[col]; v1 += bias[col + 1];
                const size_t o = (size_t)row * N + col;
                if (res) { v0 += res[o]; v1 += res[o + 1]; }
                if (relu) { v0 = fmaxf(v0, 0.f); v1 = fmaxf(v1, 0.f); }
                if (C) *(float2*)(C + o) = make_float2(v0, v1);
                if (kd) {
                    if (col >= 2048)
                        *(float2*)(vd + (size_t)row * DD + col - 2048) = make_float2(v0, v1);
                    else if (col >= 1024)
                        *(float2*)(kd + (size_t)row * DD + col - 1024) = make_float2(v0, v1);
                }
                if (Chi) {
                    *(uint32_t*)(Chi + o) = pack_hi(v0, v1);
                    *(uint32_t*)(Clo + o) = pack_lo(v0, v1);
                }
            }
        }
    }
}

// ---------------------------------------------------------------------------
// fp32 -> (hi, lo) bf16 split
// ---------------------------------------------------------------------------
__global__ __launch_bounds__(256) void cvt_hilo_k(
    const float4* __restrict__ in, uint32_t* __restrict__ hi,
    uint32_t* __restrict__ lo, int n4)
{
    int i = blockIdx.x * blockDim.x + threadIdx.x;
    if (i >= n4) return;
    float4 v = in[i];
    hi[2 * i]     = pack_hi(v.x, v.y);
    hi[2 * i + 1] = pack_hi(v.z, v.w);
    lo[2 * i]     = pack_lo(v.x, v.y);
    lo[2 * i + 1] = pack_lo(v.z, v.w);
}

// ---------------------------------------------------------------------------
// Tensor-core flash attention, causal, split-bf16 (3-term), online softmax.
// CTA = 128 queries of one (b,h); 3-buffer KV pipeline, one sync per block.
// Heavy q-tiles scheduled first (reversed blockIdx.x) for wave balance.
// ---------------------------------------------------------------------------
#define FA_SMEM (32768 + 3 * 32768)   // 128KB

__global__ __launch_bounds__(256) void flash_mma_k(
    const bf16* __restrict__ qh, const bf16* __restrict__ ql,
    bf16* __restrict__ oh, bf16* __restrict__ ol)
{
    extern __shared__ char dsm[];
    const uint32_t sb = smem_u32(dsm);
    const uint32_t Qh = sb, Ql = sb + 16384u;

    const int tid = threadIdx.x;
    const int lid = tid & 31;
    const int w   = tid >> 5;
    const int q0  = (gridDim.x - 1 - blockIdx.x) * 128;   // heavy tiles first
    const int b   = blockIdx.y >> 4;
    const int h   = blockIdx.y & 15;
    const size_t grow = (size_t)(b * SS);

    auto load_q = [&]() {
        const int row = tid >> 1;
        const int cb  = (tid & 1) * 4;
        const size_t src = (grow + q0 + row) * 3072 + h * HD;
#pragma unroll
        for (int j = 0; j < 4; ++j) {
            const int ch = cb + j;
            CP16(tile_addr(Qh, row, ch), (const char*)(qh + src + ch * 8));
            CP16(tile_addr(Ql, row, ch), (const char*)(ql + src + ch * 8));
        }
    };
    auto load_kv = [&](int buf, int k0) {
        const uint32_t bbase = sb + 32768u + (uint32_t)buf * 32768u;
        const int row = tid >> 2;
        const int cb  = (tid & 3) * 2;
        const size_t srcK = (grow + k0 + row) * 3072 + 1024 + h * HD;
        const size_t srcV = srcK + 1024;
#pragma unroll
        for (int j = 0; j < 2; ++j) {
            const int ch = cb + j;
            const uint32_t off = tile_addr(0, row, ch);
            CP16(bbase + off,           (const char*)(qh + srcK + ch * 8));
            CP16(bbase + 8192u + off,   (const char*)(ql + srcK + ch * 8));
            CP16(bbase + 16384u + off,  (const char*)(qh + srcV + ch * 8));
            CP16(bbase + 24576u + off,  (const char*)(ql + srcV + ch * 8));
        }
    };

    const int nblk = q0 / 64 + 2;

    load_q();
    load_kv(0, 0);
    CP_COMMIT();
    load_kv(1, 64);      // nblk >= 2 always
    CP_COMMIT();

    const int arow = lid & 15;
    const int achd = lid >> 4;

    uint32_t qfh[4][4], qfl[4][4];
    float of[8][4];
#pragma unroll
    for (int i = 0; i < 8; ++i)
#pragma unroll
        for (int j = 0; j < 4; ++j) of[i][j] = 0.f;
    float m0 = -1e30f, m1 = -1e30f, l0 = 0.f, l1 = 0.f;

    const int row_lo = lid >> 2;

    for (int c = 0; c < nblk; ++c) {
        if (c < nblk - 1) CP_WAIT1(); else CP_WAIT0();
        __syncthreads();
        if (c + 2 < nblk) { load_kv((c + 2) % 3, (c + 2) * 64); CP_COMMIT(); }

        if (c == 0) {
#pragma unroll
            for (int ks = 0; ks < 4; ++ks) {
                const uint32_t ad = tile_addr(Qh, w * 16 + arow, ks * 2 + achd);
                ldsm4(qfh[ks], ad);
                ldsm4(qfl[ks], ad + 16384u);
            }
        }

        const uint32_t kb = sb + 32768u + (uint32_t)(c % 3) * 32768u;
        const int k0 = c * 64;

        float sf[8][4];
#pragma unroll
        for (int i = 0; i < 8; ++i)
#pragma unroll
            for (int j = 0; j < 4; ++j) sf[i][j] = 0.f;

#pragma unroll
        for (int ks = 0; ks < 4; ++ks) {
            uint32_t bh[8][2], bl[8][2];
#pragma unroll
            for (int ntp = 0; ntp < 4; ++ntp) {
                const uint32_t bd = tile_addr(kb, ntp * 16 + arow, ks * 2 + achd);
                uint32_t t[4], u[4];
                ldsm4(t, bd);
                ldsm4(u, bd + 8192u);
                bh[2 * ntp][0] = t[0]; bh[2 * ntp][1] = t[2];
                bh[2 * ntp + 1][0] = t[1]; bh[2 * ntp + 1][1] = t[3];
                bl[2 * ntp][0] = u[0]; bl[2 * ntp][1] = u[2];
                bl[2 * ntp + 1][0] = u[1]; bl[2 * ntp + 1][1] = u[3];
            }
#pragma unroll
            for (int nt = 0; nt < 8; ++nt) mma16816(sf[nt], qfh[ks], bh[nt]);
#pragma unroll
            for (int nt = 0; nt < 8; ++nt) mma16816(sf[nt], qfh[ks], bl[nt]);
#pragma unroll
            for (int nt = 0; nt < 8; ++nt) mma16816(sf[nt], qfl[ks], bh[nt]);
        }

        const int grow0 = q0 + w * 16 + row_lo;
        const int grow1 = grow0 + 8;
        const bool need_mask = (k0 + 63 > q0 + w * 16);
#pragma unroll
        for (int nt = 0; nt < 8; ++nt) {
            const int col = k0 + nt * 8 + 2 * (lid & 3);
#pragma unroll
            for (int j = 0; j < 4; ++j) sf[nt][j] *= 0.125f;
            if (need_mask) {
                if (col     > grow0) sf[nt][0] = -1e30f;
                if (col + 1 > grow0) sf[nt][1] = -1e30f;
                if (col     > grow1) sf[nt][2] = -1e30f;
                if (col + 1 > grow1) sf[nt][3] = -1e30f;
            }
        }

        float tm0 = -1e30f, tm1 = -1e30f;
#pragma unroll
        for (int nt = 0; nt < 8; ++nt) {
            tm0 = fmaxf(tm0, fmaxf(sf[nt][0], sf[nt][1]));
            tm1 = fmaxf(tm1, fmaxf(sf[nt][2], sf[nt][3]));
        }
        tm0 = fmaxf(tm0, __shfl_xor_sync(0xffffffffu, tm0, 1));
        tm0 = fmaxf(tm0, __shfl_xor_sync(0xffffffffu, tm0, 2));
        tm1 = fmaxf(tm1, __shfl_xor_sync(0xffffffffu, tm1, 1));
        tm1 = fmaxf(tm1, __shfl_xor_sync(0xffffffffu, tm1, 2));

        const float mn0 = fmaxf(m0, tm0), mn1 = fmaxf(m1, tm1);
        const float cr0 = __expf(m0 - mn0), cr1 = __expf(m1 - mn1);
        m0 = mn0; m1 = mn1;

        float ps0 = 0.f, ps1 = 0.f;
#pragma unroll
        for (int nt = 0; nt < 8; ++nt) {
            sf[nt][0] = __expf(sf[nt][0] - mn0);
            sf[nt][1] = __expf(sf[nt][1] - mn0);
            sf[nt][2] = __expf(sf[nt][2] - mn1);
            sf[nt][3] = __expf(sf[nt][3] - mn1);
            ps0 += sf[nt][0] + sf[nt][1];
            ps1 += sf[nt][2] + sf[nt][3];
        }
        ps0 += __shfl_xor_sync(0xffffffffu, ps0, 1);
        ps0 += __shfl_xor_sync(0xffffffffu, ps0, 2);
        ps1 += __shfl_xor_sync(0xffffffffu, ps1, 1);
        ps1 += __shfl_xor_sync(0xffffffffu, ps1, 2);
        l0 = l0 * cr0 + ps0;
        l1 = l1 * cr1 + ps1;
#pragma unroll
        for (int nt = 0; nt < 8; ++nt) {
            of[nt][0] *= cr0; of[nt][1] *= cr0;
            of[nt][2] *= cr1; of[nt][3] *= cr1;
        }

        uint32_t pah[4][4], pal[4][4];
#pragma unroll
        for (int kk = 0; kk < 4; ++kk) {
            pah[kk][0] = pack_hi(sf[2 * kk][0], sf[2 * kk][1]);
            pah[kk][1] = pack_hi(sf[2 * kk][2], sf[2 * kk][3]);
            pah[kk][2] = pack_hi(sf[2 * kk + 1][0], sf[2 * kk + 1][1]);
            pah[kk][3] = pack_hi(sf[2 * kk + 1][2], sf[2 * kk + 1][3]);
            pal[kk][0] = pack_lo(sf[2 * kk][0], sf[2 * kk][1]);
            pal[kk][1] = pack_lo(sf[2 * kk][2], sf[2 * kk][3]);
            pal[kk][2] = pack_lo(sf[2 * kk + 1][0], sf[2 * kk + 1][1]);
            pal[kk][3] = pack_lo(sf[2 * kk + 1][2], sf[2 * kk + 1][3]);
        }

        const uint32_t vb = kb + 16384u;
#pragma unroll
        for (int ks = 0; ks < 4; ++ks) {
            uint32_t vh[8][2], vl[8][2];
#pragma unroll
            for (int ntp = 0; ntp < 4; ++ntp) {
                const int krow = ks * 16 + arow;
                const uint32_t vd2 = tile_addr(vb, krow, ntp * 2 + achd);
                uint32_t t[4], u[4];
                ldsm4t(t, vd2);
                ldsm4t(u, vd2 + 8192u);
                vh[2 * ntp][0] = t[0]; vh[2 * ntp][1] = t[1];
                vh[2 * ntp + 1][0] = t[2]; vh[2 * ntp + 1][1] = t[3];
                vl[2 * ntp][0] = u[0]; vl[2 * ntp][1] = u[1];
                vl[2 * ntp + 1][0] = u[2]; vl[2 * ntp + 1][1] = u[3];
            }
#pragma unroll
            for (int nt = 0; nt < 8; ++nt) mma16816(of[nt], pah[ks], vh[nt]);
#pragma unroll
            for (int nt = 0; nt < 8; ++nt) mma16816(of[nt], pah[ks], vl[nt]);
#pragma unroll
            for (int nt = 0; nt < 8; ++nt) mma16816(of[nt], pal[ks], vh[nt]);
        }
    }

    const float iv0 = 1.0f / l0, iv1 = 1.0f / l1;
    const size_t r0 = (grow + q0 + w * 16 + row_lo) * DD + h * HD;
    const size_t r1 = r0 + 8 * DD;
#pragma unroll
    for (int nt = 0; nt < 8; ++nt) {
        const int cofs = nt * 8 + 2 * (lid & 3);
        float v0 = of[nt][0] * iv0, v1 = of[nt][1] * iv0;
        float v2 = of[nt][2] * iv1, v3 = of[nt][3] * iv1;
        *(uint32_t*)(oh + r0 + cofs) = pack_hi(v0, v1);
        *(uint32_t*)(ol + r0 + cofs) = pack_lo(v0, v1);
        *(uint32_t*)(oh + r1 + cofs) = pack_hi(v2, v3);
        *(uint32_t*)(ol + r1 + cofs) = pack_lo(v2, v3);
    }
}

// ---------------------------------------------------------------------------
// LayerNorm over D=1024, optional fused bf16 hi/lo output
// ---------------------------------------------------------------------------
__global__ __launch_bounds__(256) void layernorm_k(
    const float* __restrict__ in, const float* __restrict__ w,
    const float* __restrict__ b, float* __restrict__ out,
    bf16* __restrict__ ohi, bf16* __restrict__ olo)
{
    __shared__ float red[8];
    __shared__ float bval;
    const int tid = threadIdx.x;
    const size_t base = (size_t)blockIdx.x * DD;

    float4 v = ((const float4*)(in + base))[tid];
    float s = v.x + v.y + v.z + v.w;
#pragma unroll
    for (int off = 16; off; off >>= 1) s += __shfl_xor_sync(0xffffffffu, s, off);
    if ((tid & 31) == 0) red[tid >> 5] = s;
    __syncthreads();
    if (tid == 0) {
        float t = 0.f;
#pragma unroll
        for (int i = 0; i < 8; ++i) t += red[i];
        bval = t * (1.0f / DD);
    }
    __syncthreads();
    const float mu = bval;
    __syncthreads();

    float dx = v.x - mu, dy = v.y - mu, dz = v.z - mu, dw = v.w - mu;
    float q = dx * dx + dy * dy + dz * dz + dw * dw;
#pragma unroll
    for (int off = 16; off; off >>= 1) q += __shfl_xor_sync(0xffffffffu, q, off);
    if ((tid & 31) == 0) red[tid >> 5] = q;
    __syncthreads();
    if (tid == 0) {
        float t = 0.f;
#pragma unroll
        for (int i = 0; i < 8; ++i) t += red[i];
        bval = t * (1.0f / DD);
    }
    __syncthreads();
    const float inv = rsqrtf(bval + 1e-5f);

    float4 w4 = ((const float4*)w)[tid];
    float4 b4 = ((const float4*)b)[tid];
    float4 r = make_float4(dx * inv * w4.x + b4.x,
                           dy * inv * w4.y + b4.y,
                           dz * inv * w4.z + b4.z,
                           dw * inv * w4.w + b4.w);
    ((float4*)(out + base))[tid] = r;
    if (ohi) {
        *(uint32_t*)(ohi + base + 4 * tid)     = pack_hi(r.x, r.y);
        *(uint32_t*)(ohi + base + 4 * tid + 2) = pack_hi(r.z, r.w);
        *(uint32_t*)(olo + base + 4 * tid)     = pack_lo(r.x, r.y);
        *(uint32_t*)(olo + base + 4 * tid + 2) = pack_lo(r.z, r.w);
    }
}

// ---------------------------------------------------------------------------
// Launch
// ---------------------------------------------------------------------------
static inline void cvt(const float* in, bf16* hi, bf16* lo, size_t n) {
    int n4 = (int)(n / 4);
    cvt_hilo_k<<<(n4 + 255) / 256, 256>>>((const float4*)in,
                                          (uint32_t*)hi, (uint32_t*)lo, n4);
}

extern "C" void kernel_launch(void* const* d_in, const int* in_sizes, int n_in,
                              void* d_out, int out_size)
{
    const float* x     = (const float*)d_in[0];
    const float* qkv_w = (const float*)d_in[1];
    const float* qkv_b = (const float*)d_in[2];
    const float* out_w = (const float*)d_in[3];
    const float* out_b = (const float*)d_in[4];
    const float* w1    = (const float*)d_in[5];
    const float* b1    = (const float*)d_in[6];
    const float* w2    = (const float*)d_in[7];
    const float* b2    = (const float*)d_in[8];
    const float* ln1w  = (const float*)d_in[9];
    const float* ln1b  = (const float*)d_in[10];
    const float* ln2w  = (const float*)d_in[11];
    const float* ln2b  = (const float*)d_in[12];

    float* outp = (float*)d_out;
    float* kdst = outp + (size_t)MTOK * DD;
    float* vdst = outp + (size_t)2 * MTOK * DD;

    float *h1pre, *h1, *h2pre;
    bf16 *qkvh, *qkvl, *xh, *xl, *ah, *al, *h1h, *h1l, *midh, *midl;
    bf16 *wqh, *wql, *owh, *owl, *w1h, *w1l, *w2h, *w2l;
    cudaGetSymbolAddress((void**)&qkvh,  g_qkvh); cudaGetSymbolAddress((void**)&qkvl, g_qkvl);
    cudaGetSymbolAddress((void**)&h1pre, g_h1pre);
    cudaGetSymbolAddress((void**)&h1,    g_h1);
    cudaGetSymbolAddress((void**)&h2pre, g_h2pre);
    cudaGetSymbolAddress((void**)&xh,    g_xh);   cudaGetSymbolAddress((void**)&xl, g_xl);
    cudaGetSymbolAddress((void**)&ah,    g_ah);   cudaGetSymbolAddress((void**)&al, g_al);
    cudaGetSymbolAddress((void**)&h1h,   g_h1h);  cudaGetSymbolAddress((void**)&h1l, g_h1l);
    cudaGetSymbolAddress((void**)&midh,  g_midh); cudaGetSymbolAddress((void**)&midl, g_midl);
    cudaGetSymbolAddress((void**)&wqh,   g_wqh);  cudaGetSymbolAddress((void**)&wql, g_wql);
    cudaGetSymbolAddress((void**)&owh,   g_owh);  cudaGetSymbolAddress((void**)&owl, g_owl);
    cudaGetSymbolAddress((void**)&w1h,   g_w1h);  cudaGetSymbolAddress((void**)&w1l, g_w1l);
    cudaGetSymbolAddress((void**)&w2h,   g_w2h);  cudaGetSymbolAddress((void**)&w2l, g_w2l);

    cudaFuncSetAttribute(gemm_mma,
                         cudaFuncAttributeMaxDynamicSharedMemorySize, GEMM_SMEM);
    cudaFuncSetAttribute(flash_mma_k,
                         cudaFuncAttributeMaxDynamicSharedMemorySize, FA_SMEM);

    // 0) split weights + x into bf16 hi/lo
    cvt(qkv_w, wqh, wql, (size_t)3 * DD * DD);
    cvt(out_w, owh, owl, (size_t)DD * DD);
    cvt(w1,    w1h, w1l, (size_t)FF_DIM * DD);
    cvt(w2,    w2h, w2l, (size_t)DD * FF_DIM);
    cvt(x,     xh,  xl,  (size_t)MTOK * DD);

    // 1) QKV projection -> qkv hi/lo bf16; k/v fp32 slices straight to d_out
    gemm_mma<<<dim3(3072 / 128, MTOK / 128), 256, GEMM_SMEM>>>(
        xh, xl, wqh, wql, qkv_b, nullptr, nullptr, qkvh, qkvl, kdst, vdst,
        MTOK, 3 * DD, DD, 0);
    // 2) tensor-core flash attention -> attn hi/lo bf16
    flash_mma_k<<<dim3(SS / 128, BB * HH), 256, FA_SMEM>>>(qkvh, qkvl, ah, al);
    // 3) out projection + residual x -> h1pre
    gemm_mma<<<dim3(DD / 128, MTOK / 128), 256, GEMM_SMEM>>>(
        ah, al, owh, owl, out_b, x, h1pre, nullptr, nullptr, nullptr, nullptr,
        MTOK, DD, DD, 0);
    // 4) LN1 -> h1 fp32 + hi/lo
    layernorm_k<<<MTOK, 256>>>(h1pre, ln1w, ln1b, h1, h1h, h1l);
    // 5) MLP up + ReLU -> mid hi/lo only
    gemm_mma<<<dim3(FF_DIM / 128, MTOK / 128), 256, GEMM_SMEM>>>(
        h1h, h1l, w1h, w1l, b1, nullptr, nullptr, midh, midl, nullptr, nullptr,
        MTOK, FF_DIM, DD, 1);
    // 6) MLP down + residual h1 -> h2pre
    gemm_mma<<<dim3(DD / 128, MTOK / 128), 256, GEMM_SMEM>>>(
        midh, midl, w2h, w2l, b2, h1, h2pre, nullptr, nullptr, nullptr, nullptr,
        MTOK, DD, FF_DIM, 0);
    // 7) LN2 -> out
    layernorm_k<<<MTOK, 256>>>(h2pre, ln2w, ln2b, outp, nullptr, nullptr);
}

// round 8
// speedup vs baseline: 1.2368x; 1.1964x over previous
#include <cuda_runtime.h>
#include <cuda_bf16.h>
#include <cuda_fp16.h>
#include <cstdint>

// Problem constants: B=2, S=2048, D=1024, H=16, hd=64, FF=4096
#define BB 2
#define SS 2048
#define DD 1024
#define HH 16
#define HD 64
#define FF_DIM 4096
#define MTOK (BB*SS)          // 4096 rows

typedef __nv_bfloat16 bf16;

// ---------------------------------------------------------------------------
// Scratch (device globals; no allocation allowed)
// ---------------------------------------------------------------------------
__device__ bf16 g_qkvh[(size_t)MTOK * 3 * DD], g_qkvl[(size_t)MTOK * 3 * DD];
__device__ float g_h1pre[(size_t)MTOK * DD];
__device__ float g_h1[(size_t)MTOK * DD];
__device__ float g_h2pre[(size_t)MTOK * DD];

__device__ bf16 g_xh[(size_t)MTOK * DD],      g_xl[(size_t)MTOK * DD];
__device__ bf16 g_ah[(size_t)MTOK * DD],      g_al[(size_t)MTOK * DD];   // attn out
__device__ bf16 g_wqh[(size_t)3 * DD * DD],   g_wql[(size_t)3 * DD * DD];
__device__ bf16 g_owh[(size_t)DD * DD],       g_owl[(size_t)DD * DD];

// fp16 2-term MLP path
__device__ __half g_h1f[(size_t)MTOK * DD];                 // LN1 out, fp16
__device__ __half g_midf[(size_t)MTOK * FF_DIM];            // relu(mid), fp16
__device__ __half g_w1hf[(size_t)FF_DIM * DD], g_w1lf[(size_t)FF_DIM * DD];
__device__ __half g_w2hf[(size_t)DD * FF_DIM], g_w2lf[(size_t)DD * FF_DIM];

// ---------------------------------------------------------------------------
// MMA / ldmatrix / cp.async helpers
// ---------------------------------------------------------------------------
__device__ __forceinline__ uint32_t smem_u32(const void* p) {
    uint32_t a;
    asm("{ .reg .u64 t; cvta.to.shared.u64 t, %1; cvt.u32.u64 %0, t; }"
        : "=r"(a) : "l"(p));
    return a;
}
__device__ __forceinline__ void ldsm4(uint32_t* r, uint32_t a) {
    asm volatile("ldmatrix.sync.aligned.m8n8.x4.shared.b16 {%0,%1,%2,%3}, [%4];"
                 : "=r"(r[0]), "=r"(r[1]), "=r"(r[2]), "=r"(r[3]) : "r"(a));
}
__device__ __forceinline__ void ldsm4t(uint32_t* r, uint32_t a) {
    asm volatile("ldmatrix.sync.aligned.m8n8.x4.trans.shared.b16 {%0,%1,%2,%3}, [%4];"
                 : "=r"(r[0]), "=r"(r[1]), "=r"(r[2]), "=r"(r[3]) : "r"(a));
}
__device__ __forceinline__ void mma16816(float* c, const uint32_t* a, const uint32_t* b) {
    asm volatile(
        "mma.sync.aligned.m16n8k16.row.col.f32.bf16.bf16.f32 "
        "{%0,%1,%2,%3}, {%4,%5,%6,%7}, {%8,%9}, {%0,%1,%2,%3};"
        : "+f"(c[0]), "+f"(c[1]), "+f"(c[2]), "+f"(c[3])
        : "r"(a[0]), "r"(a[1]), "r"(a[2]), "r"(a[3]), "r"(b[0]), "r"(b[1]));
}
__device__ __forceinline__ void mma16816h(float* c, const uint32_t* a, const uint32_t* b) {
    asm volatile(
        "mma.sync.aligned.m16n8k16.row.col.f32.f16.f16.f32 "
        "{%0,%1,%2,%3}, {%4,%5,%6,%7}, {%8,%9}, {%0,%1,%2,%3};"
        : "+f"(c[0]), "+f"(c[1]), "+f"(c[2]), "+f"(c[3])
        : "r"(a[0]), "r"(a[1]), "r"(a[2]), "r"(a[3]), "r"(b[0]), "r"(b[1]));
}
#define CP16(dst, src) \
    asm volatile("cp.async.cg.shared.global [%0], [%1], 16;" :: "r"(dst), "l"(src) : "memory")
#define CP_COMMIT() asm volatile("cp.async.commit_group;" ::: "memory")
#define CP_WAIT1()  asm volatile("cp.async.wait_group 1;" ::: "memory")
#define CP_WAIT0()  asm volatile("cp.async.wait_group 0;" ::: "memory")

// 128B-row tile (flash): row stride 128B, chunk ch swizzled by row&7.
__device__ __forceinline__ uint32_t tile_addr(uint32_t base, int row, int ch) {
    return base + (uint32_t)row * 128u + (uint32_t)((ch ^ (row & 7)) << 4);
}
// paired-row tile (gemm): [128][32] 16-bit elems in 64 smem rows of 128B.
__device__ __forceinline__ uint32_t tile2_addr(uint32_t base, int r, int k) {
    const int s = r >> 1;
    const int c = ((r & 1) << 2) | k;
    return base + (uint32_t)s * 128u + (uint32_t)((c ^ (s & 7)) << 4);
}
__device__ __forceinline__ uint32_t pack_hi(float a, float b) {
    __nv_bfloat162 h = __halves2bfloat162(__float2bfloat16(a), __float2bfloat16(b));
    return *(uint32_t*)&h;
}
__device__ __forceinline__ uint32_t pack_lo(float a, float b) {
    bf16 ha = __float2bfloat16(a), hb = __float2bfloat16(b);
    __nv_bfloat162 l = __halves2bfloat162(__float2bfloat16(a - __bfloat162float(ha)),
                                          __float2bfloat16(b - __bfloat162float(hb)));
    return *(uint32_t*)&l;
}
__device__ __forceinline__ uint32_t pack_h2(float a, float b) {
    __half2 h = __halves2half2(__float2half(a), __float2half(b));
    return *(uint32_t*)&h;
}

// ---------------------------------------------------------------------------
// Split-bf16 3-term GEMM (unchanged from R7): used for QKV and out-proj.
// ---------------------------------------------------------------------------
#define GEMM_SMEM (3 * 32768)   // 96KB

__global__ __launch_bounds__(256, 2) void gemm_mma(
    const bf16* __restrict__ Ah, const bf16* __restrict__ Al,
    const bf16* __restrict__ Wh, const bf16* __restrict__ Wl,
    const float* __restrict__ bias, const float* __restrict__ res,
    float* __restrict__ C, bf16* __restrict__ Chi, bf16* __restrict__ Clo,
    float* __restrict__ kd, float* __restrict__ vd,
    int M, int N, int K, int relu)
{
    extern __shared__ char dsm[];
    const uint32_t sb = smem_u32(dsm);

    const int tid = threadIdx.x;
    const int lid = tid & 31;
    const int wid = tid >> 5;
    const int wm = wid & 1;
    const int wn = wid >> 1;
    const int bm = blockIdx.y * 128, bn = blockIdx.x * 128;

    const bf16* gs[4] = { Ah + (size_t)bm * K, Al + (size_t)bm * K,
                          Wh + (size_t)bn * K, Wl + (size_t)bn * K };

    float acc[4][4][4];
#pragma unroll
    for (int i = 0; i < 4; ++i)
#pragma unroll
        for (int j = 0; j < 4; ++j)
#pragma unroll
            for (int k = 0; k < 4; ++k) acc[i][j][k] = 0.f;

    const int NC = K >> 5;

    auto load_stage = [&](int stage, int kk) {
        const uint32_t stb = sb + (uint32_t)stage * 32768u;
        const int r  = tid >> 1;
        const int k0 = (tid & 1) * 2;
#pragma unroll
        for (int t4 = 0; t4 < 4; ++t4) {
            const uint32_t tb = stb + (uint32_t)t4 * 8192u;
            const bf16* g = gs[t4] + kk + (size_t)r * K;
#pragma unroll
            for (int j = 0; j < 2; ++j)
                CP16(tile2_addr(tb, r, k0 + j), (const char*)(g + (k0 + j) * 8));
        }
        CP_COMMIT();
    };

    load_stage(0, 0);
    load_stage(1, 32);

    const int arow = lid & 15;
    const int achd = lid >> 4;

    for (int c = 0; c < NC; ++c) {
        if (c < NC - 1) CP_WAIT1(); else CP_WAIT0();
        __syncthreads();
        if (c + 2 < NC) load_stage((c + 2) % 3, (c + 2) << 5);

        const uint32_t stb = sb + (uint32_t)(c % 3) * 32768u;

#pragma unroll
        for (int ks = 0; ks < 2; ++ks) {
            const int chk = ks * 2 + achd;
            uint32_t ah[4][4], al[4][4];
#pragma unroll
            for (int mt = 0; mt < 4; ++mt) {
                const int r = wm * 64 + mt * 16 + arow;
                ldsm4(ah[mt], tile2_addr(stb, r, chk));
                ldsm4(al[mt], tile2_addr(stb + 8192u, r, chk));
            }
            uint32_t bh[4][2], bl[4][2];
#pragma unroll
            for (int ntp = 0; ntp < 2; ++ntp) {
                const int r = wn * 32 + ntp * 16 + arow;
                uint32_t t[4], u[4];
                ldsm4(t, tile2_addr(stb + 16384u, r, chk));
                ldsm4(u, tile2_addr(stb + 24576u, r, chk));
                bh[2 * ntp][0] = t[0]; bh[2 * ntp][1] = t[2];
                bh[2 * ntp + 1][0] = t[1]; bh[2 * ntp + 1][1] = t[3];
                bl[2 * ntp][0] = u[0]; bl[2 * ntp][1] = u[2];
                bl[2 * ntp + 1][0] = u[1]; bl[2 * ntp + 1][1] = u[3];
            }
#pragma unroll
            for (int mt = 0; mt < 4; ++mt)
#pragma unroll
                for (int nt = 0; nt < 4; ++nt)
                    mma16816(acc[mt][nt], ah[mt], bh[nt]);
#pragma unroll
            for (int mt = 0; mt < 4; ++mt)
#pragma unroll
                for (int nt = 0; nt < 4; ++nt)
                    mma16816(acc[mt][nt], ah[mt], bl[nt]);
#pragma unroll
            for (int mt = 0; mt < 4; ++mt)
#pragma unroll
                for (int nt = 0; nt < 4; ++nt)
                    mma16816(acc[mt][nt], al[mt], bh[nt]);
        }
    }

    const int l4 = lid >> 2;
    const int l2 = (lid & 3) * 2;
#pragma unroll
    for (int mt = 0; mt < 4; ++mt) {
#pragma unroll
        for (int nt = 0; nt < 4; ++nt) {
            const int col = bn + wn * 32 + nt * 8 + l2;
#pragma unroll
            for (int half = 0; half < 2; ++half) {
                const int row = bm + wm * 64 + mt * 16 + l4 + half * 8;
                float v0 = acc[mt][nt][2 * half + 0];
                float v1 = acc[mt][nt][2 * half + 1];
                v0 += bias[col]; v1 += bias[col + 1];
                const size_t o = (size_t)row * N + col;
                if (res) { v0 += res[o]; v1 += res[o + 1]; }
                if (relu) { v0 = fmaxf(v0, 0.f); v1 = fmaxf(v1, 0.f); }
                if (C) *(float2*)(C + o) = make_float2(v0, v1);
                if (kd) {
                    if (col >= 2048)
                        *(float2*)(vd + (size_t)row * DD + col - 2048) = make_float2(v0, v1);
                    else if (col >= 1024)
                        *(float2*)(kd + (size_t)row * DD + col - 1024) = make_float2(v0, v1);
                }
                if (Chi) {
                    *(uint32_t*)(Chi + o) = pack_hi(v0, v1);
                    *(uint32_t*)(Clo + o) = pack_lo(v0, v1);
                }
            }
        }
    }
}

// ---------------------------------------------------------------------------
// fp16 2-term GEMM: C = A_f16 @ (Wh+Wl)_f16^T + bias (+res) (+relu).
// A single tile, W hi/lo: 3 tiles x 8KB = 24KB/stage, 3 stages = 72KB.
// 2/3 the MMA count of the 3-term bf16 kernel. Used for both MLP GEMMs.
// ---------------------------------------------------------------------------
#define GEMMF_SMEM (3 * 24576)   // 72KB

__global__ __launch_bounds__(256, 2) void gemm_f16_2t(
    const __half* __restrict__ A,
    const __half* __restrict__ Wh, const __half* __restrict__ Wl,
    const float* __restrict__ bias, const float* __restrict__ res,
    float* __restrict__ C, __half* __restrict__ Cf,
    int M, int N, int K, int relu)
{
    extern __shared__ char dsm[];
    const uint32_t sb = smem_u32(dsm);

    const int tid = threadIdx.x;
    const int lid = tid & 31;
    const int wid = tid >> 5;
    const int wm = wid & 1;
    const int wn = wid >> 1;
    const int bm = blockIdx.y * 128, bn = blockIdx.x * 128;

    const __half* gs[3] = { A + (size_t)bm * K, Wh + (size_t)bn * K, Wl + (size_t)bn * K };

    float acc[4][4][4];
#pragma unroll
    for (int i = 0; i < 4; ++i)
#pragma unroll
        for (int j = 0; j < 4; ++j)
#pragma unroll
            for (int k = 0; k < 4; ++k) acc[i][j][k] = 0.f;

    const int NC = K >> 5;

    auto load_stage = [&](int stage, int kk) {
        const uint32_t stb = sb + (uint32_t)stage * 24576u;
        const int r  = tid >> 1;
        const int k0 = (tid & 1) * 2;
#pragma unroll
        for (int t3 = 0; t3 < 3; ++t3) {
            const uint32_t tb = stb + (uint32_t)t3 * 8192u;
            const __half* g = gs[t3] + kk + (size_t)r * K;
#pragma unroll
            for (int j = 0; j < 2; ++j)
                CP16(tile2_addr(tb, r, k0 + j), (const char*)(g + (k0 + j) * 8));
        }
        CP_COMMIT();
    };

    load_stage(0, 0);
    load_stage(1, 32);

    const int arow = lid & 15;
    const int achd = lid >> 4;

    for (int c = 0; c < NC; ++c) {
        if (c < NC - 1) CP_WAIT1(); else CP_WAIT0();
        __syncthreads();
        if (c + 2 < NC) load_stage((c + 2) % 3, (c + 2) << 5);

        const uint32_t stb = sb + (uint32_t)(c % 3) * 24576u;

#pragma unroll
        for (int ks = 0; ks < 2; ++ks) {
            const int chk = ks * 2 + achd;
            uint32_t af[4][4];
#pragma unroll
            for (int mt = 0; mt < 4; ++mt) {
                const int r = wm * 64 + mt * 16 + arow;
                ldsm4(af[mt], tile2_addr(stb, r, chk));
            }
            uint32_t bh[4][2], bl[4][2];
#pragma unroll
            for (int ntp = 0; ntp < 2; ++ntp) {
                const int r = wn * 32 + ntp * 16 + arow;
                uint32_t t[4], u[4];
                ldsm4(t, tile2_addr(stb + 8192u, r, chk));
                ldsm4(u, tile2_addr(stb + 16384u, r, chk));
                bh[2 * ntp][0] = t[0]; bh[2 * ntp][1] = t[2];
                bh[2 * ntp + 1][0] = t[1]; bh[2 * ntp + 1][1] = t[3];
                bl[2 * ntp][0] = u[0]; bl[2 * ntp][1] = u[2];
                bl[2 * ntp + 1][0] = u[1]; bl[2 * ntp + 1][1] = u[3];
            }
#pragma unroll
            for (int mt = 0; mt < 4; ++mt)
#pragma unroll
                for (int nt = 0; nt < 4; ++nt)
                    mma16816h(acc[mt][nt], af[mt], bh[nt]);
#pragma unroll
            for (int mt = 0; mt < 4; ++mt)
#pragma unroll
                for (int nt = 0; nt < 4; ++nt)
                    mma16816h(acc[mt][nt], af[mt], bl[nt]);
        }
    }

    const int l4 = lid >> 2;
    const int l2 = (lid & 3) * 2;
#pragma unroll
    for (int mt = 0; mt < 4; ++mt) {
#pragma unroll
        for (int nt = 0; nt < 4; ++nt) {
            const int col = bn + wn * 32 + nt * 8 + l2;
#pragma unroll
            for (int half = 0; half < 2; ++half) {
                const int row = bm + wm * 64 + mt * 16 + l4 + half * 8;
                float v0 = acc[mt][nt][2 * half + 0];
                float v1 = acc[mt][nt][2 * half + 1];
                v0 += bias[col]; v1 += bias[col + 1];
                const size_t o = (size_t)row * N + col;
                if (res) { v0 += res[o]; v1 += res[o + 1]; }
                if (relu) { v0 = fmaxf(v0, 0.f); v1 = fmaxf(v1, 0.f); }
                if (C) *(float2*)(C + o) = make_float2(v0, v1);
                if (Cf) *(uint32_t*)(Cf + o) = pack_h2(v0, v1);
            }
        }
    }
}

// ---------------------------------------------------------------------------
// fp32 -> (hi, lo) bf16 split
// ---------------------------------------------------------------------------
__global__ __launch_bounds__(256) void cvt_hilo_k(
    const float4* __restrict__ in, uint32_t* __restrict__ hi,
    uint32_t* __restrict__ lo, int n4)
{
    int i = blockIdx.x * blockDim.x + threadIdx.x;
    if (i >= n4) return;
    float4 v = in[i];
    hi[2 * i]     = pack_hi(v.x, v.y);
    hi[2 * i + 1] = pack_hi(v.z, v.w);
    lo[2 * i]     = pack_lo(v.x, v.y);
    lo[2 * i + 1] = pack_lo(v.z, v.w);
}

// fp32 -> (hi, lo) fp16 split
__global__ __launch_bounds__(256) void cvt_f16_hilo_k(
    const float4* __restrict__ in, uint32_t* __restrict__ hi,
    uint32_t* __restrict__ lo, int n4)
{
    int i = blockIdx.x * blockDim.x + threadIdx.x;
    if (i >= n4) return;
    float4 v = in[i];
    __half hx = __float2half(v.x), hy = __float2half(v.y);
    __half hz = __float2half(v.z), hw = __float2half(v.w);
    __half2 a = __halves2half2(hx, hy), b = __halves2half2(hz, hw);
    hi[2 * i]     = *(uint32_t*)&a;
    hi[2 * i + 1] = *(uint32_t*)&b;
    __half2 c = __halves2half2(__float2half(v.x - __half2float(hx)),
                               __float2half(v.y - __half2float(hy)));
    __half2 d = __halves2half2(__float2half(v.z - __half2float(hz)),
                               __float2half(v.w - __half2float(hw)));
    lo[2 * i]     = *(uint32_t*)&c;
    lo[2 * i + 1] = *(uint32_t*)&d;
}

// ---------------------------------------------------------------------------
// Tensor-core flash attention (unchanged from R7)
// ---------------------------------------------------------------------------
#define FA_SMEM (32768 + 3 * 32768)   // 128KB

__global__ __launch_bounds__(256) void flash_mma_k(
    const bf16* __restrict__ qh, const bf16* __restrict__ ql,
    bf16* __restrict__ oh, bf16* __restrict__ ol)
{
    extern __shared__ char dsm[];
    const uint32_t sb = smem_u32(dsm);
    const uint32_t Qh = sb, Ql = sb + 16384u;

    const int tid = threadIdx.x;
    const int lid = tid & 31;
    const int w   = tid >> 5;
    const int q0  = (gridDim.x - 1 - blockIdx.x) * 128;
    const int b   = blockIdx.y >> 4;
    const int h   = blockIdx.y & 15;
    const size_t grow = (size_t)(b * SS);

    auto load_q = [&]() {
        const int row = tid >> 1;
        const int cb  = (tid & 1) * 4;
        const size_t src = (grow + q0 + row) * 3072 + h * HD;
#pragma unroll
        for (int j = 0; j < 4; ++j) {
            const int ch = cb + j;
            CP16(tile_addr(Qh, row, ch), (const char*)(qh + src + ch * 8));
            CP16(tile_addr(Ql, row, ch), (const char*)(ql + src + ch * 8));
        }
    };
    auto load_kv = [&](int buf, int k0) {
        const uint32_t bbase = sb + 32768u + (uint32_t)buf * 32768u;
        const int row = tid >> 2;
        const int cb  = (tid & 3) * 2;
        const size_t srcK = (grow + k0 + row) * 3072 + 1024 + h * HD;
        const size_t srcV = srcK + 1024;
#pragma unroll
        for (int j = 0; j < 2; ++j) {
            const int ch = cb + j;
            const uint32_t off = tile_addr(0, row, ch);
            CP16(bbase + off,           (const char*)(qh + srcK + ch * 8));
            CP16(bbase + 8192u + off,   (const char*)(ql + srcK + ch * 8));
            CP16(bbase + 16384u + off,  (const char*)(qh + srcV + ch * 8));
            CP16(bbase + 24576u + off,  (const char*)(ql + srcV + ch * 8));
        }
    };

    const int nblk = q0 / 64 + 2;

    load_q();
    load_kv(0, 0);
    CP_COMMIT();
    load_kv(1, 64);
    CP_COMMIT();

    const int arow = lid & 15;
    const int achd = lid >> 4;

    uint32_t qfh[4][4], qfl[4][4];
    float of[8][4];
#pragma unroll
    for (int i = 0; i < 8; ++i)
#pragma unroll
        for (int j = 0; j < 4; ++j) of[i][j] = 0.f;
    float m0 = -1e30f, m1 = -1e30f, l0 = 0.f, l1 = 0.f;

    const int row_lo = lid >> 2;

    for (int c = 0; c < nblk; ++c) {
        if (c < nblk - 1) CP_WAIT1(); else CP_WAIT0();
        __syncthreads();
        if (c + 2 < nblk) { load_kv((c + 2) % 3, (c + 2) * 64); CP_COMMIT(); }

        if (c == 0) {
#pragma unroll
            for (int ks = 0; ks < 4; ++ks) {
                const uint32_t ad = tile_addr(Qh, w * 16 + arow, ks * 2 + achd);
                ldsm4(qfh[ks], ad);
                ldsm4(qfl[ks], ad + 16384u);
            }
        }

        const uint32_t kb = sb + 32768u + (uint32_t)(c % 3) * 32768u;
        const int k0 = c * 64;

        float sf[8][4];
#pragma unroll
        for (int i = 0; i < 8; ++i)
#pragma unroll
            for (int j = 0; j < 4; ++j) sf[i][j] = 0.f;

#pragma unroll
        for (int ks = 0; ks < 4; ++ks) {
            uint32_t bh[8][2], bl[8][2];
#pragma unroll
            for (int ntp = 0; ntp < 4; ++ntp) {
                const uint32_t bd = tile_addr(kb, ntp * 16 + arow, ks * 2 + achd);
                uint32_t t[4], u[4];
                ldsm4(t, bd);
                ldsm4(u, bd + 8192u);
                bh[2 * ntp][0] = t[0]; bh[2 * ntp][1] = t[2];
                bh[2 * ntp + 1][0] = t[1]; bh[2 * ntp + 1][1] = t[3];
                bl[2 * ntp][0] = u[0]; bl[2 * ntp][1] = u[2];
                bl[2 * ntp + 1][0] = u[1]; bl[2 * ntp + 1][1] = u[3];
            }
#pragma unroll
            for (int nt = 0; nt < 8; ++nt) mma16816(sf[nt], qfh[ks], bh[nt]);
#pragma unroll
            for (int nt = 0; nt < 8; ++nt) mma16816(sf[nt], qfh[ks], bl[nt]);
#pragma unroll
            for (int nt = 0; nt < 8; ++nt) mma16816(sf[nt], qfl[ks], bh[nt]);
        }

        const int grow0 = q0 + w * 16 + row_lo;
        const int grow1 = grow0 + 8;
        const bool need_mask = (k0 + 63 > q0 + w * 16);
#pragma unroll
        for (int nt = 0; nt < 8; ++nt) {
            const int col = k0 + nt * 8 + 2 * (lid & 3);
#pragma unroll
            for (int j = 0; j < 4; ++j) sf[nt][j] *= 0.125f;
            if (need_mask) {
                if (col     > grow0) sf[nt][0] = -1e30f;
                if (col + 1 > grow0) sf[nt][1] = -1e30f;
                if (col     > grow1) sf[nt][2] = -1e30f;
                if (col + 1 > grow1) sf[nt][3] = -1e30f;
            }
        }

        float tm0 = -1e30f, tm1 = -1e30f;
#pragma unroll
        for (int nt = 0; nt < 8; ++nt) {
            tm0 = fmaxf(tm0, fmaxf(sf[nt][0], sf[nt][1]));
            tm1 = fmaxf(tm1, fmaxf(sf[nt][2], sf[nt][3]));
        }
        tm0 = fmaxf(tm0, __shfl_xor_sync(0xffffffffu, tm0, 1));
        tm0 = fmaxf(tm0, __shfl_xor_sync(0xffffffffu, tm0, 2));
        tm1 = fmaxf(tm1, __shfl_xor_sync(0xffffffffu, tm1, 1));
        tm1 = fmaxf(tm1, __shfl_xor_sync(0xffffffffu, tm1, 2));

        const float mn0 = fmaxf(m0, tm0), mn1 = fmaxf(m1, tm1);
        const float cr0 = __expf(m0 - mn0), cr1 = __expf(m1 - mn1);
        m0 = mn0; m1 = mn1;

        float ps0 = 0.f, ps1 = 0.f;
#pragma unroll
        for (int nt = 0; nt < 8; ++nt) {
            sf[nt][0] = __expf(sf[nt][0] - mn0);
            sf[nt][1] = __expf(sf[nt][1] - mn0);
            sf[nt][2] = __expf(sf[nt][2] - mn1);
            sf[nt][3] = __expf(sf[nt][3] - mn1);
            ps0 += sf[nt][0] + sf[nt][1];
            ps1 += sf[nt][2] + sf[nt][3];
        }
        ps0 += __shfl_xor_sync(0xffffffffu, ps0, 1);
        ps0 += __shfl_xor_sync(0xffffffffu, ps0, 2);
        ps1 += __shfl_xor_sync(0xffffffffu, ps1, 1);
        ps1 += __shfl_xor_sync(0xffffffffu, ps1, 2);
        l0 = l0 * cr0 + ps0;
        l1 = l1 * cr1 + ps1;
#pragma unroll
        for (int nt = 0; nt < 8; ++nt) {
            of[nt][0] *= cr0; of[nt][1] *= cr0;
            of[nt][2] *= cr1; of[nt][3] *= cr1;
        }

        uint32_t pah[4][4], pal[4][4];
#pragma unroll
        for (int kk = 0; kk < 4; ++kk) {
            pah[kk][0] = pack_hi(sf[2 * kk][0], sf[2 * kk][1]);
            pah[kk][1] = pack_hi(sf[2 * kk][2], sf[2 * kk][3]);
            pah[kk][2] = pack_hi(sf[2 * kk + 1][0], sf[2 * kk + 1][1]);
            pah[kk][3] = pack_hi(sf[2 * kk + 1][2], sf[2 * kk + 1][3]);
            pal[kk][0] = pack_lo(sf[2 * kk][0], sf[2 * kk][1]);
            pal[kk][1] = pack_lo(sf[2 * kk][2], sf[2 * kk][3]);
            pal[kk][2] = pack_lo(sf[2 * kk + 1][0], sf[2 * kk + 1][1]);
            pal[kk][3] = pack_lo(sf[2 * kk + 1][2], sf[2 * kk + 1][3]);
        }

        const uint32_t vb = kb + 16384u;
#pragma unroll
        for (int ks = 0; ks < 4; ++ks) {
            uint32_t vh[8][2], vl[8][2];
#pragma unroll
            for (int ntp = 0; ntp < 4; ++ntp) {
                const int krow = ks * 16 + arow;
                const uint32_t vd2 = tile_addr(vb, krow, ntp * 2 + achd);
                uint32_t t[4], u[4];
                ldsm4t(t, vd2);
                ldsm4t(u, vd2 + 8192u);
                vh[2 * ntp][0] = t[0]; vh[2 * ntp][1] = t[1];
                vh[2 * ntp + 1][0] = t[2]; vh[2 * ntp + 1][1] = t[3];
                vl[2 * ntp][0] = u[0]; vl[2 * ntp][1] = u[1];
                vl[2 * ntp + 1][0] = u[2]; vl[2 * ntp + 1][1] = u[3];
            }
#pragma unroll
            for (int nt = 0; nt < 8; ++nt) mma16816(of[nt], pah[ks], vh[nt]);
#pragma unroll
            for (int nt = 0; nt < 8; ++nt) mma16816(of[nt], pah[ks], vl[nt]);
#pragma unroll
            for (int nt = 0; nt < 8; ++nt) mma16816(of[nt], pal[ks], vh[nt]);
        }
    }

    const float iv0 = 1.0f / l0, iv1 = 1.0f / l1;
    const size_t r0 = (grow + q0 + w * 16 + row_lo) * DD + h * HD;
    const size_t r1 = r0 + 8 * DD;
#pragma unroll
    for (int nt = 0; nt < 8; ++nt) {
        const int cofs = nt * 8 + 2 * (lid & 3);
        float v0 = of[nt][0] * iv0, v1 = of[nt][1] * iv0;
        float v2 = of[nt][2] * iv1, v3 = of[nt][3] * iv1;
        *(uint32_t*)(oh + r0 + cofs) = pack_hi(v0, v1);
        *(uint32_t*)(ol + r0 + cofs) = pack_lo(v0, v1);
        *(uint32_t*)(oh + r1 + cofs) = pack_hi(v2, v3);
        *(uint32_t*)(ol + r1 + cofs) = pack_lo(v2, v3);
    }
}

// ---------------------------------------------------------------------------
// LayerNorm over D=1024; optional fused fp16 single output (for MLP path)
// ---------------------------------------------------------------------------
__global__ __launch_bounds__(256) void layernorm_k(
    const float* __restrict__ in, const float* __restrict__ w,
    const float* __restrict__ b, float* __restrict__ out,
    __half* __restrict__ of16)
{
    __shared__ float red[8];
    __shared__ float bval;
    const int tid = threadIdx.x;
    const size_t base = (size_t)blockIdx.x * DD;

    float4 v = ((const float4*)(in + base))[tid];
    float s = v.x + v.y + v.z + v.w;
#pragma unroll
    for (int off = 16; off; off >>= 1) s += __shfl_xor_sync(0xffffffffu, s, off);
    if ((tid & 31) == 0) red[tid >> 5] = s;
    __syncthreads();
    if (tid == 0) {
        float t = 0.f;
#pragma unroll
        for (int i = 0; i < 8; ++i) t += red[i];
        bval = t * (1.0f / DD);
    }
    __syncthreads();
    const float mu = bval;
    __syncthreads();

    float dx = v.x - mu, dy = v.y - mu, dz = v.z - mu, dw = v.w - mu;
    float q = dx * dx + dy * dy + dz * dz + dw * dw;
#pragma unroll
    for (int off = 16; off; off >>= 1) q += __shfl_xor_sync(0xffffffffu, q, off);
    if ((tid & 31) == 0) red[tid >> 5] = q;
    __syncthreads();
    if (tid == 0) {
        float t = 0.f;
#pragma unroll
        for (int i = 0; i < 8; ++i) t += red[i];
        bval = t * (1.0f / DD);
    }
    __syncthreads();
    const float inv = rsqrtf(bval + 1e-5f);

    float4 w4 = ((const float4*)w)[tid];
    float4 b4 = ((const float4*)b)[tid];
    float4 r = make_float4(dx * inv * w4.x + b4.x,
                           dy * inv * w4.y + b4.y,
                           dz * inv * w4.z + b4.z,
                           dw * inv * w4.w + b4.w);
    ((float4*)(out + base))[tid] = r;
    if (of16) {
        *(uint32_t*)(of16 + base + 4 * tid)     = pack_h2(r.x, r.y);
        *(uint32_t*)(of16 + base + 4 * tid + 2) = pack_h2(r.z, r.w);
    }
}

// ---------------------------------------------------------------------------
// Launch
// ---------------------------------------------------------------------------
static inline void cvt(const float* in, bf16* hi, bf16* lo, size_t n) {
    int n4 = (int)(n / 4);
    cvt_hilo_k<<<(n4 + 255) / 256, 256>>>((const float4*)in,
                                          (uint32_t*)hi, (uint32_t*)lo, n4);
}
static inline void cvtf(const float* in, __half* hi, __half* lo, size_t n) {
    int n4 = (int)(n / 4);
    cvt_f16_hilo_k<<<(n4 + 255) / 256, 256>>>((const float4*)in,
                                              (uint32_t*)hi, (uint32_t*)lo, n4);
}

extern "C" void kernel_launch(void* const* d_in, const int* in_sizes, int n_in,
                              void* d_out, int out_size)
{
    const float* x     = (const float*)d_in[0];
    const float* qkv_w = (const float*)d_in[1];
    const float* qkv_b = (const float*)d_in[2];
    const float* out_w = (const float*)d_in[3];
    const float* out_b = (const float*)d_in[4];
    const float* w1    = (const float*)d_in[5];
    const float* b1    = (const float*)d_in[6];
    const float* w2    = (const float*)d_in[7];
    const float* b2    = (const float*)d_in[8];
    const float* ln1w  = (const float*)d_in[9];
    const float* ln1b  = (const float*)d_in[10];
    const float* ln2w  = (const float*)d_in[11];
    const float* ln2b  = (const float*)d_in[12];

    float* outp = (float*)d_out;
    float* kdst = outp + (size_t)MTOK * DD;
    float* vdst = outp + (size_t)2 * MTOK * DD;

    float *h1pre, *h1, *h2pre;
    bf16 *qkvh, *qkvl, *xh, *xl, *ah, *al, *wqh, *wql, *owh, *owl;
    __half *h1f, *midf, *w1hf, *w1lf, *w2hf, *w2lf;
    cudaGetSymbolAddress((void**)&qkvh,  g_qkvh); cudaGetSymbolAddress((void**)&qkvl, g_qkvl);
    cudaGetSymbolAddress((void**)&h1pre, g_h1pre);
    cudaGetSymbolAddress((void**)&h1,    g_h1);
    cudaGetSymbolAddress((void**)&h2pre, g_h2pre);
    cudaGetSymbolAddress((void**)&xh,    g_xh);   cudaGetSymbolAddress((void**)&xl, g_xl);
    cudaGetSymbolAddress((void**)&ah,    g_ah);   cudaGetSymbolAddress((void**)&al, g_al);
    cudaGetSymbolAddress((void**)&wqh,   g_wqh);  cudaGetSymbolAddress((void**)&wql, g_wql);
    cudaGetSymbolAddress((void**)&owh,   g_owh);  cudaGetSymbolAddress((void**)&owl, g_owl);
    cudaGetSymbolAddress((void**)&h1f,   g_h1f);
    cudaGetSymbolAddress((void**)&midf,  g_midf);
    cudaGetSymbolAddress((void**)&w1hf,  g_w1hf); cudaGetSymbolAddress((void**)&w1lf, g_w1lf);
    cudaGetSymbolAddress((void**)&w2hf,  g_w2hf); cudaGetSymbolAddress((void**)&w2lf, g_w2lf);

    cudaFuncSetAttribute(gemm_mma,
                         cudaFuncAttributeMaxDynamicSharedMemorySize, GEMM_SMEM);
    cudaFuncSetAttribute(gemm_f16_2t,
                         cudaFuncAttributeMaxDynamicSharedMemorySize, GEMMF_SMEM);
    cudaFuncSetAttribute(flash_mma_k,
                         cudaFuncAttributeMaxDynamicSharedMemorySize, FA_SMEM);

    // 0) weight/input splits
    cvt(qkv_w, wqh, wql, (size_t)3 * DD * DD);
    cvt(out_w, owh, owl, (size_t)DD * DD);
    cvtf(w1,   w1hf, w1lf, (size_t)FF_DIM * DD);
    cvtf(w2,   w2hf, w2lf, (size_t)DD * FF_DIM);
    cvt(x,     xh,  xl,  (size_t)MTOK * DD);

    // 1) QKV projection (bf16 3-term) -> qkv hi/lo; k/v fp32 slices to d_out
    gemm_mma<<<dim3(3072 / 128, MTOK / 128), 256, GEMM_SMEM>>>(
        xh, xl, wqh, wql, qkv_b, nullptr, nullptr, qkvh, qkvl, kdst, vdst,
        MTOK, 3 * DD, DD, 0);
    // 2) flash attention (bf16 3-term) -> attn hi/lo
    flash_mma_k<<<dim3(SS / 128, BB * HH), 256, FA_SMEM>>>(qkvh, qkvl, ah, al);
    // 3) out projection (bf16 3-term) + residual x -> h1pre
    gemm_mma<<<dim3(DD / 128, MTOK / 128), 256, GEMM_SMEM>>>(
        ah, al, owh, owl, out_b, x, h1pre, nullptr, nullptr, nullptr, nullptr,
        MTOK, DD, DD, 0);
    // 4) LN1 -> h1 fp32 + h1f fp16
    layernorm_k<<<MTOK, 256>>>(h1pre, ln1w, ln1b, h1, h1f);
    // 5) MLP up (fp16 2-term) + ReLU -> midf fp16
    gemm_f16_2t<<<dim3(FF_DIM / 128, MTOK / 128), 256, GEMMF_SMEM>>>(
        h1f, w1hf, w1lf, b1, nullptr, nullptr, midf,
        MTOK, FF_DIM, DD, 1);
    // 6) MLP down (fp16 2-term) + residual h1 -> h2pre fp32
    gemm_f16_2t<<<dim3(DD / 128, MTOK / 128), 256, GEMMF_SMEM>>>(
        midf, w2hf, w2lf, b2, h1, h2pre, nullptr,
        MTOK, DD, FF_DIM, 0);
    // 7) LN2 -> out
    layernorm_k<<<MTOK, 256>>>(h2pre, ln2w, ln2b, outp, nullptr);
}

// round 9
// speedup vs baseline: 1.4740x; 1.1918x over previous
#include <cuda_runtime.h>
#include <cuda_bf16.h>
#include <cuda_fp16.h>
#include <cstdint>

// Problem constants: B=2, S=2048, D=1024, H=16, hd=64, FF=4096
#define BB 2
#define SS 2048
#define DD 1024
#define HH 16
#define HD 64
#define FF_DIM 4096
#define MTOK (BB*SS)          // 4096 rows

// ---------------------------------------------------------------------------
// Scratch (device globals; no allocation allowed) — all-fp16 pipeline
// ---------------------------------------------------------------------------
__device__ __half g_qkvfh[(size_t)MTOK * 3 * DD], g_qkvfl[(size_t)MTOK * 3 * DD];
__device__ __half g_af[(size_t)MTOK * DD];         // attn out, fp16 single
__device__ float  g_h1pre[(size_t)MTOK * DD];
__device__ float  g_h1[(size_t)MTOK * DD];
__device__ float  g_h2pre[(size_t)MTOK * DD];
__device__ __half g_h1f[(size_t)MTOK * DD];
__device__ __half g_midf[(size_t)MTOK * FF_DIM];
__device__ __half g_xf[(size_t)MTOK * DD];
__device__ __half g_wqhf[(size_t)3 * DD * DD], g_wqlf[(size_t)3 * DD * DD];
__device__ __half g_owhf[(size_t)DD * DD],     g_owlf[(size_t)DD * DD];
__device__ __half g_w1hf[(size_t)FF_DIM * DD], g_w1lf[(size_t)FF_DIM * DD];
__device__ __half g_w2hf[(size_t)DD * FF_DIM], g_w2lf[(size_t)DD * FF_DIM];

// ---------------------------------------------------------------------------
// MMA / ldmatrix / cp.async helpers
// ---------------------------------------------------------------------------
__device__ __forceinline__ uint32_t smem_u32(const void* p) {
    uint32_t a;
    asm("{ .reg .u64 t; cvta.to.shared.u64 t, %1; cvt.u32.u64 %0, t; }"
        : "=r"(a) : "l"(p));
    return a;
}
__device__ __forceinline__ void ldsm4(uint32_t* r, uint32_t a) {
    asm volatile("ldmatrix.sync.aligned.m8n8.x4.shared.b16 {%0,%1,%2,%3}, [%4];"
                 : "=r"(r[0]), "=r"(r[1]), "=r"(r[2]), "=r"(r[3]) : "r"(a));
}
__device__ __forceinline__ void ldsm4t(uint32_t* r, uint32_t a) {
    asm volatile("ldmatrix.sync.aligned.m8n8.x4.trans.shared.b16 {%0,%1,%2,%3}, [%4];"
                 : "=r"(r[0]), "=r"(r[1]), "=r"(r[2]), "=r"(r[3]) : "r"(a));
}
__device__ __forceinline__ void mma16816h(float* c, const uint32_t* a, const uint32_t* b) {
    asm volatile(
        "mma.sync.aligned.m16n8k16.row.col.f32.f16.f16.f32 "
        "{%0,%1,%2,%3}, {%4,%5,%6,%7}, {%8,%9}, {%0,%1,%2,%3};"
        : "+f"(c[0]), "+f"(c[1]), "+f"(c[2]), "+f"(c[3])
        : "r"(a[0]), "r"(a[1]), "r"(a[2]), "r"(a[3]), "r"(b[0]), "r"(b[1]));
}
#define CP16(dst, src) \
    asm volatile("cp.async.cg.shared.global [%0], [%1], 16;" :: "r"(dst), "l"(src) : "memory")
#define CP_COMMIT() asm volatile("cp.async.commit_group;" ::: "memory")
#define CP_WAIT1()  asm volatile("cp.async.wait_group 1;" ::: "memory")
#define CP_WAIT0()  asm volatile("cp.async.wait_group 0;" ::: "memory")

// 128B-row tile (flash): row stride 128B, chunk ch swizzled by row&7.
__device__ __forceinline__ uint32_t tile_addr(uint32_t base, int row, int ch) {
    return base + (uint32_t)row * 128u + (uint32_t)((ch ^ (row & 7)) << 4);
}
// paired-row tile (gemm): [128][32] 16-bit elems in 64 smem rows of 128B.
__device__ __forceinline__ uint32_t tile2_addr(uint32_t base, int r, int k) {
    const int s = r >> 1;
    const int c = ((r & 1) << 2) | k;
    return base + (uint32_t)s * 128u + (uint32_t)((c ^ (s & 7)) << 4);
}
__device__ __forceinline__ uint32_t pack_h2(float a, float b) {
    __half2 h = __halves2half2(__float2half(a), __float2half(b));
    return *(uint32_t*)&h;
}
__device__ __forceinline__ uint32_t pack_h2lo(float a, float b) {
    __half ha = __float2half(a), hb = __float2half(b);
    __half2 l = __halves2half2(__float2half(a - __half2float(ha)),
                               __float2half(b - __half2float(hb)));
    return *(uint32_t*)&l;
}

// ---------------------------------------------------------------------------
// fp16 2-term GEMM: C = A_f16 @ (Wh+Wl)_f16^T + bias (+res) (+relu).
// 128x128 CTA tile, 8 warps (2Mx4N), K-stage 32, 3-stage pipeline, 72KB smem.
// Optional outputs: fp32 C, fp16 hi (Cfh) / lo (Cfl), fused fp32 kv-cache.
// ---------------------------------------------------------------------------
#define GEMMF_SMEM (3 * 24576)   // 72KB

__global__ __launch_bounds__(256, 2) void gemm_f16_2t(
    const __half* __restrict__ A,
    const __half* __restrict__ Wh, const __half* __restrict__ Wl,
    const float* __restrict__ bias, const float* __restrict__ res,
    float* __restrict__ C, __half* __restrict__ Cfh, __half* __restrict__ Cfl,
    float* __restrict__ kd, float* __restrict__ vd,
    int M, int N, int K, int relu)
{
    extern __shared__ char dsm[];
    const uint32_t sb = smem_u32(dsm);

    const int tid = threadIdx.x;
    const int lid = tid & 31;
    const int wid = tid >> 5;
    const int wm = wid & 1;
    const int wn = wid >> 1;
    const int bm = blockIdx.y * 128, bn = blockIdx.x * 128;

    const __half* gs[3] = { A + (size_t)bm * K, Wh + (size_t)bn * K, Wl + (size_t)bn * K };

    float acc[4][4][4];
#pragma unroll
    for (int i = 0; i < 4; ++i)
#pragma unroll
        for (int j = 0; j < 4; ++j)
#pragma unroll
            for (int k = 0; k < 4; ++k) acc[i][j][k] = 0.f;

    const int NC = K >> 5;

    auto load_stage = [&](int stage, int kk) {
        const uint32_t stb = sb + (uint32_t)stage * 24576u;
        const int r  = tid >> 1;
        const int k0 = (tid & 1) * 2;
#pragma unroll
        for (int t3 = 0; t3 < 3; ++t3) {
            const uint32_t tb = stb + (uint32_t)t3 * 8192u;
            const __half* g = gs[t3] + kk + (size_t)r * K;
#pragma unroll
            for (int j = 0; j < 2; ++j)
                CP16(tile2_addr(tb, r, k0 + j), (const char*)(g + (k0 + j) * 8));
        }
        CP_COMMIT();
    };

    load_stage(0, 0);
    load_stage(1, 32);

    const int arow = lid & 15;
    const int achd = lid >> 4;

    for (int c = 0; c < NC; ++c) {
        if (c < NC - 1) CP_WAIT1(); else CP_WAIT0();
        __syncthreads();
        if (c + 2 < NC) load_stage((c + 2) % 3, (c + 2) << 5);

        const uint32_t stb = sb + (uint32_t)(c % 3) * 24576u;

#pragma unroll
        for (int ks = 0; ks < 2; ++ks) {
            const int chk = ks * 2 + achd;
            uint32_t af[4][4];
#pragma unroll
            for (int mt = 0; mt < 4; ++mt) {
                const int r = wm * 64 + mt * 16 + arow;
                ldsm4(af[mt], tile2_addr(stb, r, chk));
            }
            uint32_t bh[4][2], bl[4][2];
#pragma unroll
            for (int ntp = 0; ntp < 2; ++ntp) {
                const int r = wn * 32 + ntp * 16 + arow;
                uint32_t t[4], u[4];
                ldsm4(t, tile2_addr(stb + 8192u, r, chk));
                ldsm4(u, tile2_addr(stb + 16384u, r, chk));
                bh[2 * ntp][0] = t[0]; bh[2 * ntp][1] = t[2];
                bh[2 * ntp + 1][0] = t[1]; bh[2 * ntp + 1][1] = t[3];
                bl[2 * ntp][0] = u[0]; bl[2 * ntp][1] = u[2];
                bl[2 * ntp + 1][0] = u[1]; bl[2 * ntp + 1][1] = u[3];
            }
#pragma unroll
            for (int mt = 0; mt < 4; ++mt)
#pragma unroll
                for (int nt = 0; nt < 4; ++nt)
                    mma16816h(acc[mt][nt], af[mt], bh[nt]);
#pragma unroll
            for (int mt = 0; mt < 4; ++mt)
#pragma unroll
                for (int nt = 0; nt < 4; ++nt)
                    mma16816h(acc[mt][nt], af[mt], bl[nt]);
        }
    }

    const int l4 = lid >> 2;
    const int l2 = (lid & 3) * 2;
#pragma unroll
    for (int mt = 0; mt < 4; ++mt) {
#pragma unroll
        for (int nt = 0; nt < 4; ++nt) {
            const int col = bn + wn * 32 + nt * 8 + l2;
#pragma unroll
            for (int half = 0; half < 2; ++half) {
                const int row = bm + wm * 64 + mt * 16 + l4 + half * 8;
                float v0 = acc[mt][nt][2 * half + 0];
                float v1 = acc[mt][nt][2 * half + 1];
                v0 += bias[col]; v1 += bias[col + 1];
                const size_t o = (size_t)row * N + col;
                if (res) { v0 += res[o]; v1 += res[o + 1]; }
                if (relu) { v0 = fmaxf(v0, 0.f); v1 = fmaxf(v1, 0.f); }
                if (C) *(float2*)(C + o) = make_float2(v0, v1);
                if (kd) {
                    if (col >= 2048)
                        *(float2*)(vd + (size_t)row * DD + col - 2048) = make_float2(v0, v1);
                    else if (col >= 1024)
                        *(float2*)(kd + (size_t)row * DD + col - 1024) = make_float2(v0, v1);
                }
                if (Cfh) *(uint32_t*)(Cfh + o) = pack_h2(v0, v1);
                if (Cfl) *(uint32_t*)(Cfl + o) = pack_h2lo(v0, v1);
            }
        }
    }
}

// ---------------------------------------------------------------------------
// fp32 -> fp16 hi/lo split (weights) and fp32 -> fp16 single (x)
// ---------------------------------------------------------------------------
__global__ __launch_bounds__(256) void cvt_f16_hilo_k(
    const float4* __restrict__ in, uint32_t* __restrict__ hi,
    uint32_t* __restrict__ lo, int n4)
{
    int i = blockIdx.x * blockDim.x + threadIdx.x;
    if (i >= n4) return;
    float4 v = in[i];
    hi[2 * i]     = pack_h2(v.x, v.y);
    hi[2 * i + 1] = pack_h2(v.z, v.w);
    lo[2 * i]     = pack_h2lo(v.x, v.y);
    lo[2 * i + 1] = pack_h2lo(v.z, v.w);
}
__global__ __launch_bounds__(256) void cvt_f16_k(
    const float4* __restrict__ in, uint32_t* __restrict__ o, int n4)
{
    int i = blockIdx.x * blockDim.x + threadIdx.x;
    if (i >= n4) return;
    float4 v = in[i];
    o[2 * i]     = pack_h2(v.x, v.y);
    o[2 * i + 1] = pack_h2(v.z, v.w);
}

// ---------------------------------------------------------------------------
// fp16 2-term flash attention, causal, online softmax.
// Q single fp16 (hi only); K,V 2-term (hi+lo). Emits fp16 single attn.
// CTA = 128 queries of one (b,h); 3-buffer KV pipeline, one sync per block.
// ---------------------------------------------------------------------------
#define FA_SMEM (16384 + 3 * 32768)   // 112KB

__global__ __launch_bounds__(256) void flash_f16_k(
    const __half* __restrict__ qh, const __half* __restrict__ ql,
    __half* __restrict__ out)
{
    extern __shared__ char dsm[];
    const uint32_t sb = smem_u32(dsm);
    const uint32_t Qt = sb;                       // Q hi tile, 16KB

    const int tid = threadIdx.x;
    const int lid = tid & 31;
    const int w   = tid >> 5;
    const int q0  = (gridDim.x - 1 - blockIdx.x) * 128;   // heavy tiles first
    const int b   = blockIdx.y >> 4;
    const int h   = blockIdx.y & 15;
    const size_t grow = (size_t)(b * SS);

    auto load_q = [&]() {
        const int row = tid >> 1;
        const int cb  = (tid & 1) * 4;
        const size_t src = (grow + q0 + row) * 3072 + h * HD;
#pragma unroll
        for (int j = 0; j < 4; ++j) {
            const int ch = cb + j;
            CP16(tile_addr(Qt, row, ch), (const char*)(qh + src + ch * 8));
        }
    };
    auto load_kv = [&](int buf, int k0) {
        const uint32_t bbase = sb + 16384u + (uint32_t)buf * 32768u;
        const int row = tid >> 2;
        const int cb  = (tid & 3) * 2;
        const size_t srcK = (grow + k0 + row) * 3072 + 1024 + h * HD;
        const size_t srcV = srcK + 1024;
#pragma unroll
        for (int j = 0; j < 2; ++j) {
            const int ch = cb + j;
            const uint32_t off = tile_addr(0, row, ch);
            CP16(bbase + off,           (const char*)(qh + srcK + ch * 8));
            CP16(bbase + 8192u + off,   (const char*)(ql + srcK + ch * 8));
            CP16(bbase + 16384u + off,  (const char*)(qh + srcV + ch * 8));
            CP16(bbase + 24576u + off,  (const char*)(ql + srcV + ch * 8));
        }
    };

    const int nblk = q0 / 64 + 2;

    load_q();
    load_kv(0, 0);
    CP_COMMIT();
    load_kv(1, 64);
    CP_COMMIT();

    const int arow = lid & 15;
    const int achd = lid >> 4;

    uint32_t qf[4][4];
    float of[8][4];
#pragma unroll
    for (int i = 0; i < 8; ++i)
#pragma unroll
        for (int j = 0; j < 4; ++j) of[i][j] = 0.f;
    float m0 = -1e30f, m1 = -1e30f, l0 = 0.f, l1 = 0.f;

    const int row_lo = lid >> 2;

    for (int c = 0; c < nblk; ++c) {
        if (c < nblk - 1) CP_WAIT1(); else CP_WAIT0();
        __syncthreads();
        if (c + 2 < nblk) { load_kv((c + 2) % 3, (c + 2) * 64); CP_COMMIT(); }

        if (c == 0) {
#pragma unroll
            for (int ks = 0; ks < 4; ++ks)
                ldsm4(qf[ks], tile_addr(Qt, w * 16 + arow, ks * 2 + achd));
        }

        const uint32_t kb = sb + 16384u + (uint32_t)(c % 3) * 32768u;
        const int k0 = c * 64;

        float sf[8][4];
#pragma unroll
        for (int i = 0; i < 8; ++i)
#pragma unroll
            for (int j = 0; j < 4; ++j) sf[i][j] = 0.f;

#pragma unroll
        for (int ks = 0; ks < 4; ++ks) {
            uint32_t bh[8][2], bl[8][2];
#pragma unroll
            for (int ntp = 0; ntp < 4; ++ntp) {
                const uint32_t bd = tile_addr(kb, ntp * 16 + arow, ks * 2 + achd);
                uint32_t t[4], u[4];
                ldsm4(t, bd);
                ldsm4(u, bd + 8192u);
                bh[2 * ntp][0] = t[0]; bh[2 * ntp][1] = t[2];
                bh[2 * ntp + 1][0] = t[1]; bh[2 * ntp + 1][1] = t[3];
                bl[2 * ntp][0] = u[0]; bl[2 * ntp][1] = u[2];
                bl[2 * ntp + 1][0] = u[1]; bl[2 * ntp + 1][1] = u[3];
            }
#pragma unroll
            for (int nt = 0; nt < 8; ++nt) mma16816h(sf[nt], qf[ks], bh[nt]);
#pragma unroll
            for (int nt = 0; nt < 8; ++nt) mma16816h(sf[nt], qf[ks], bl[nt]);
        }

        const int grow0 = q0 + w * 16 + row_lo;
        const int grow1 = grow0 + 8;
        const bool need_mask = (k0 + 63 > q0 + w * 16);
#pragma unroll
        for (int nt = 0; nt < 8; ++nt) {
            const int col = k0 + nt * 8 + 2 * (lid & 3);
#pragma unroll
            for (int j = 0; j < 4; ++j) sf[nt][j] *= 0.125f;
            if (need_mask) {
                if (col     > grow0) sf[nt][0] = -1e30f;
                if (col + 1 > grow0) sf[nt][1] = -1e30f;
                if (col     > grow1) sf[nt][2] = -1e30f;
                if (col + 1 > grow1) sf[nt][3] = -1e30f;
            }
        }

        float tm0 = -1e30f, tm1 = -1e30f;
#pragma unroll
        for (int nt = 0; nt < 8; ++nt) {
            tm0 = fmaxf(tm0, fmaxf(sf[nt][0], sf[nt][1]));
            tm1 = fmaxf(tm1, fmaxf(sf[nt][2], sf[nt][3]));
        }
        tm0 = fmaxf(tm0, __shfl_xor_sync(0xffffffffu, tm0, 1));
        tm0 = fmaxf(tm0, __shfl_xor_sync(0xffffffffu, tm0, 2));
        tm1 = fmaxf(tm1, __shfl_xor_sync(0xffffffffu, tm1, 1));
        tm1 = fmaxf(tm1, __shfl_xor_sync(0xffffffffu, tm1, 2));

        const float mn0 = fmaxf(m0, tm0), mn1 = fmaxf(m1, tm1);
        const float cr0 = __expf(m0 - mn0), cr1 = __expf(m1 - mn1);
        m0 = mn0; m1 = mn1;

        float ps0 = 0.f, ps1 = 0.f;
#pragma unroll
        for (int nt = 0; nt < 8; ++nt) {
            sf[nt][0] = __expf(sf[nt][0] - mn0);
            sf[nt][1] = __expf(sf[nt][1] - mn0);
            sf[nt][2] = __expf(sf[nt][2] - mn1);
            sf[nt][3] = __expf(sf[nt][3] - mn1);
            ps0 += sf[nt][0] + sf[nt][1];
            ps1 += sf[nt][2] + sf[nt][3];
        }
        ps0 += __shfl_xor_sync(0xffffffffu, ps0, 1);
        ps0 += __shfl_xor_sync(0xffffffffu, ps0, 2);
        ps1 += __shfl_xor_sync(0xffffffffu, ps1, 1);
        ps1 += __shfl_xor_sync(0xffffffffu, ps1, 2);
        l0 = l0 * cr0 + ps0;
        l1 = l1 * cr1 + ps1;
#pragma unroll
        for (int nt = 0; nt < 8; ++nt) {
            of[nt][0] *= cr0; of[nt][1] *= cr0;
            of[nt][2] *= cr1; of[nt][3] *= cr1;
        }

        // P -> fp16 single A-fragments (C layout == A layout)
        uint32_t pa[4][4];
#pragma unroll
        for (int kk = 0; kk < 4; ++kk) {
            pa[kk][0] = pack_h2(sf[2 * kk][0], sf[2 * kk][1]);
            pa[kk][1] = pack_h2(sf[2 * kk][2], sf[2 * kk][3]);
            pa[kk][2] = pack_h2(sf[2 * kk + 1][0], sf[2 * kk + 1][1]);
            pa[kk][3] = pack_h2(sf[2 * kk + 1][2], sf[2 * kk + 1][3]);
        }

        const uint32_t vb = kb + 16384u;
#pragma unroll
        for (int ks = 0; ks < 4; ++ks) {
            uint32_t vh[8][2], vl[8][2];
#pragma unroll
            for (int ntp = 0; ntp < 4; ++ntp) {
                const int krow = ks * 16 + arow;
                const uint32_t vd2 = tile_addr(vb, krow, ntp * 2 + achd);
                uint32_t t[4], u[4];
                ldsm4t(t, vd2);
                ldsm4t(u, vd2 + 8192u);
                vh[2 * ntp][0] = t[0]; vh[2 * ntp][1] = t[1];
                vh[2 * ntp + 1][0] = t[2]; vh[2 * ntp + 1][1] = t[3];
                vl[2 * ntp][0] = u[0]; vl[2 * ntp][1] = u[1];
                vl[2 * ntp + 1][0] = u[2]; vl[2 * ntp + 1][1] = u[3];
            }
#pragma unroll
            for (int nt = 0; nt < 8; ++nt) mma16816h(of[nt], pa[ks], vh[nt]);
#pragma unroll
            for (int nt = 0; nt < 8; ++nt) mma16816h(of[nt], pa[ks], vl[nt]);
        }
    }

    const float iv0 = 1.0f / l0, iv1 = 1.0f / l1;
    const size_t r0 = (grow + q0 + w * 16 + row_lo) * DD + h * HD;
    const size_t r1 = r0 + 8 * DD;
#pragma unroll
    for (int nt = 0; nt < 8; ++nt) {
        const int cofs = nt * 8 + 2 * (lid & 3);
        *(uint32_t*)(out + r0 + cofs) = pack_h2(of[nt][0] * iv0, of[nt][1] * iv0);
        *(uint32_t*)(out + r1 + cofs) = pack_h2(of[nt][2] * iv1, of[nt][3] * iv1);
    }
}

// ---------------------------------------------------------------------------
// LayerNorm over D=1024; optional fused fp16 single output
// ---------------------------------------------------------------------------
__global__ __launch_bounds__(256) void layernorm_k(
    const float* __restrict__ in, const float* __restrict__ w,
    const float* __restrict__ b, float* __restrict__ out,
    __half* __restrict__ of16)
{
    __shared__ float red[8];
    __shared__ float bval;
    const int tid = threadIdx.x;
    const size_t base = (size_t)blockIdx.x * DD;

    float4 v = ((const float4*)(in + base))[tid];
    float s = v.x + v.y + v.z + v.w;
#pragma unroll
    for (int off = 16; off; off >>= 1) s += __shfl_xor_sync(0xffffffffu, s, off);
    if ((tid & 31) == 0) red[tid >> 5] = s;
    __syncthreads();
    if (tid == 0) {
        float t = 0.f;
#pragma unroll
        for (int i = 0; i < 8; ++i) t += red[i];
        bval = t * (1.0f / DD);
    }
    __syncthreads();
    const float mu = bval;
    __syncthreads();

    float dx = v.x - mu, dy = v.y - mu, dz = v.z - mu, dw = v.w - mu;
    float q = dx * dx + dy * dy + dz * dz + dw * dw;
#pragma unroll
    for (int off = 16; off; off >>= 1) q += __shfl_xor_sync(0xffffffffu, q, off);
    if ((tid & 31) == 0) red[tid >> 5] = q;
    __syncthreads();
    if (tid == 0) {
        float t = 0.f;
#pragma unroll
        for (int i = 0; i < 8; ++i) t += red[i];
        bval = t * (1.0f / DD);
    }
    __syncthreads();
    const float inv = rsqrtf(bval + 1e-5f);

    float4 w4 = ((const float4*)w)[tid];
    float4 b4 = ((const float4*)b)[tid];
    float4 r = make_float4(dx * inv * w4.x + b4.x,
                           dy * inv * w4.y + b4.y,
                           dz * inv * w4.z + b4.z,
                           dw * inv * w4.w + b4.w);
    ((float4*)(out + base))[tid] = r;
    if (of16) {
        *(uint32_t*)(of16 + base + 4 * tid)     = pack_h2(r.x, r.y);
        *(uint32_t*)(of16 + base + 4 * tid + 2) = pack_h2(r.z, r.w);
    }
}

// ---------------------------------------------------------------------------
// Launch
// ---------------------------------------------------------------------------
static inline void cvtf(const float* in, __half* hi, __half* lo, size_t n) {
    int n4 = (int)(n / 4);
    cvt_f16_hilo_k<<<(n4 + 255) / 256, 256>>>((const float4*)in,
                                              (uint32_t*)hi, (uint32_t*)lo, n4);
}

extern "C" void kernel_launch(void* const* d_in, const int* in_sizes, int n_in,
                              void* d_out, int out_size)
{
    const float* x     = (const float*)d_in[0];
    const float* qkv_w = (const float*)d_in[1];
    const float* qkv_b = (const float*)d_in[2];
    const float* out_w = (const float*)d_in[3];
    const float* out_b = (const float*)d_in[4];
    const float* w1    = (const float*)d_in[5];
    const float* b1    = (const float*)d_in[6];
    const float* w2    = (const float*)d_in[7];
    const float* b2    = (const float*)d_in[8];
    const float* ln1w  = (const float*)d_in[9];
    const float* ln1b  = (const float*)d_in[10];
    const float* ln2w  = (const float*)d_in[11];
    const float* ln2b  = (const float*)d_in[12];

    float* outp = (float*)d_out;
    float* kdst = outp + (size_t)MTOK * DD;
    float* vdst = outp + (size_t)2 * MTOK * DD;

    float *h1pre, *h1, *h2pre;
    __half *qkvfh, *qkvfl, *af, *h1f, *midf, *xf;
    __half *wqhf, *wqlf, *owhf, *owlf, *w1hf, *w1lf, *w2hf, *w2lf;
    cudaGetSymbolAddress((void**)&qkvfh, g_qkvfh); cudaGetSymbolAddress((void**)&qkvfl, g_qkvfl);
    cudaGetSymbolAddress((void**)&af,    g_af);
    cudaGetSymbolAddress((void**)&h1pre, g_h1pre);
    cudaGetSymbolAddress((void**)&h1,    g_h1);
    cudaGetSymbolAddress((void**)&h2pre, g_h2pre);
    cudaGetSymbolAddress((void**)&h1f,   g_h1f);
    cudaGetSymbolAddress((void**)&midf,  g_midf);
    cudaGetSymbolAddress((void**)&xf,    g_xf);
    cudaGetSymbolAddress((void**)&wqhf,  g_wqhf); cudaGetSymbolAddress((void**)&wqlf, g_wqlf);
    cudaGetSymbolAddress((void**)&owhf,  g_owhf); cudaGetSymbolAddress((void**)&owlf, g_owlf);
    cudaGetSymbolAddress((void**)&w1hf,  g_w1hf); cudaGetSymbolAddress((void**)&w1lf, g_w1lf);
    cudaGetSymbolAddress((void**)&w2hf,  g_w2hf); cudaGetSymbolAddress((void**)&w2lf, g_w2lf);

    cudaFuncSetAttribute(gemm_f16_2t,
                         cudaFuncAttributeMaxDynamicSharedMemorySize, GEMMF_SMEM);
    cudaFuncSetAttribute(flash_f16_k,
                         cudaFuncAttributeMaxDynamicSharedMemorySize, FA_SMEM);

    // 0) weight hi/lo splits + x single fp16
    cvtf(qkv_w, wqhf, wqlf, (size_t)3 * DD * DD);
    cvtf(out_w, owhf, owlf, (size_t)DD * DD);
    cvtf(w1,    w1hf, w1lf, (size_t)FF_DIM * DD);
    cvtf(w2,    w2hf, w2lf, (size_t)DD * FF_DIM);
    {
        int n4 = MTOK * DD / 4;
        cvt_f16_k<<<(n4 + 255) / 256, 256>>>((const float4*)x, (uint32_t*)xf, n4);
    }

    // 1) QKV projection (fp16 2-term) -> qkv fp16 hi/lo; k/v fp32 to d_out
    gemm_f16_2t<<<dim3(3072 / 128, MTOK / 128), 256, GEMMF_SMEM>>>(
        xf, wqhf, wqlf, qkv_b, nullptr, nullptr, qkvfh, qkvfl, kdst, vdst,
        MTOK, 3 * DD, DD, 0);
    // 2) flash attention (fp16 2-term) -> attn fp16 single
    flash_f16_k<<<dim3(SS / 128, BB * HH), 256, FA_SMEM>>>(qkvfh, qkvfl, af);
    // 3) out projection (fp16 2-term) + residual x -> h1pre
    gemm_f16_2t<<<dim3(DD / 128, MTOK / 128), 256, GEMMF_SMEM>>>(
        af, owhf, owlf, out_b, x, h1pre, nullptr, nullptr, nullptr, nullptr,
        MTOK, DD, DD, 0);
    // 4) LN1 -> h1 fp32 + h1f fp16
    layernorm_k<<<MTOK, 256>>>(h1pre, ln1w, ln1b, h1, h1f);
    // 5) MLP up (fp16 2-term) + ReLU -> midf fp16
    gemm_f16_2t<<<dim3(FF_DIM / 128, MTOK / 128), 256, GEMMF_SMEM>>>(
        h1f, w1hf, w1lf, b1, nullptr, nullptr, midf, nullptr, nullptr, nullptr,
        MTOK, FF_DIM, DD, 1);
    // 6) MLP down (fp16 2-term) + residual h1 -> h2pre fp32
    gemm_f16_2t<<<dim3(DD / 128, MTOK / 128), 256, GEMMF_SMEM>>>(
        midf, w2hf, w2lf, b2, h1, h2pre, nullptr, nullptr, nullptr, nullptr,
        MTOK, DD, FF_DIM, 0);
    // 7) LN2 -> out
    layernorm_k<<<MTOK, 256>>>(h2pre, ln2w, ln2b, outp, nullptr);
}

// round 10
// speedup vs baseline: 2.0620x; 1.3989x over previous
#include <cuda_runtime.h>
#include <cuda_fp16.h>
#include <cstdint>

// Problem constants: B=2, S=2048, D=1024, H=16, hd=64, FF=4096
#define BB 2
#define SS 2048
#define DD 1024
#define HH 16
#define HD 64
#define FF_DIM 4096
#define MTOK (BB*SS)          // 4096 rows

// ---------------------------------------------------------------------------
// Scratch (device globals; no allocation allowed)
// ---------------------------------------------------------------------------
__device__ __half g_qkvf[(size_t)MTOK * 3 * DD];   // qkv, fp16 single
__device__ __half g_af[(size_t)MTOK * DD];         // attn out, fp16 single
__device__ float  g_h1pre[(size_t)MTOK * DD];
__device__ float  g_h1[(size_t)MTOK * DD];
__device__ float  g_h2pre[(size_t)MTOK * DD];
__device__ __half g_h1f[(size_t)MTOK * DD];
__device__ __half g_midf[(size_t)MTOK * FF_DIM];
__device__ __half g_xf[(size_t)MTOK * DD];
__device__ __half g_wqhf[(size_t)3 * DD * DD], g_wqlf[(size_t)3 * DD * DD];
__device__ __half g_owhf[(size_t)DD * DD],     g_owlf[(size_t)DD * DD];
__device__ __half g_w1f[(size_t)FF_DIM * DD];
__device__ __half g_w2f[(size_t)DD * FF_DIM];

// ---------------------------------------------------------------------------
// MMA / ldmatrix / cp.async helpers
// ---------------------------------------------------------------------------
__device__ __forceinline__ uint32_t smem_u32(const void* p) {
    uint32_t a;
    asm("{ .reg .u64 t; cvta.to.shared.u64 t, %1; cvt.u32.u64 %0, t; }"
        : "=r"(a) : "l"(p));
    return a;
}
__device__ __forceinline__ void ldsm4(uint32_t* r, uint32_t a) {
    asm volatile("ldmatrix.sync.aligned.m8n8.x4.shared.b16 {%0,%1,%2,%3}, [%4];"
                 : "=r"(r[0]), "=r"(r[1]), "=r"(r[2]), "=r"(r[3]) : "r"(a));
}
__device__ __forceinline__ void ldsm4t(uint32_t* r, uint32_t a) {
    asm volatile("ldmatrix.sync.aligned.m8n8.x4.trans.shared.b16 {%0,%1,%2,%3}, [%4];"
                 : "=r"(r[0]), "=r"(r[1]), "=r"(r[2]), "=r"(r[3]) : "r"(a));
}
__device__ __forceinline__ void mma16816h(float* c, const uint32_t* a, const uint32_t* b) {
    asm volatile(
        "mma.sync.aligned.m16n8k16.row.col.f32.f16.f16.f32 "
        "{%0,%1,%2,%3}, {%4,%5,%6,%7}, {%8,%9}, {%0,%1,%2,%3};"
        : "+f"(c[0]), "+f"(c[1]), "+f"(c[2]), "+f"(c[3])
        : "r"(a[0]), "r"(a[1]), "r"(a[2]), "r"(a[3]), "r"(b[0]), "r"(b[1]));
}
#define CP16(dst, src) \
    asm volatile("cp.async.cg.shared.global [%0], [%1], 16;" :: "r"(dst), "l"(src) : "memory")
#define CP_COMMIT() asm volatile("cp.async.commit_group;" ::: "memory")
#define CP_WAIT1()  asm volatile("cp.async.wait_group 1;" ::: "memory")
#define CP_WAIT0()  asm volatile("cp.async.wait_group 0;" ::: "memory")

// 128B-row tile (flash): row stride 128B, chunk ch swizzled by row&7.
__device__ __forceinline__ uint32_t tile_addr(uint32_t base, int row, int ch) {
    return base + (uint32_t)row * 128u + (uint32_t)((ch ^ (row & 7)) << 4);
}
// paired-row tile (gemm): [128][32] 16-bit elems in 64 smem rows of 128B.
__device__ __forceinline__ uint32_t tile2_addr(uint32_t base, int r, int k) {
    const int s = r >> 1;
    const int c = ((r & 1) << 2) | k;
    return base + (uint32_t)s * 128u + (uint32_t)((c ^ (s & 7)) << 4);
}
__device__ __forceinline__ uint32_t pack_h2(float a, float b) {
    __half2 h = __halves2half2(__float2half(a), __float2half(b));
    return *(uint32_t*)&h;
}
__device__ __forceinline__ uint32_t pack_h2lo(float a, float b) {
    __half ha = __float2half(a), hb = __float2half(b);
    __half2 l = __halves2half2(__float2half(a - __half2float(ha)),
                               __float2half(b - __half2float(hb)));
    return *(uint32_t*)&l;
}

// ---------------------------------------------------------------------------
// fp16 2-term GEMM (A single, W hi+lo). Used for QKV and out-proj.
// 128x128 CTA tile, 8 warps (2Mx4N), K-stage 32, 3-stage pipeline, 72KB smem.
// ---------------------------------------------------------------------------
#define GEMMF_SMEM (3 * 24576)   // 72KB

__global__ __launch_bounds__(256, 2) void gemm_f16_2t(
    const __half* __restrict__ A,
    const __half* __restrict__ Wh, const __half* __restrict__ Wl,
    const float* __restrict__ bias, const float* __restrict__ res,
    float* __restrict__ C, __half* __restrict__ Cf,
    float* __restrict__ kd, float* __restrict__ vd,
    int M, int N, int K, int relu)
{
    extern __shared__ char dsm[];
    const uint32_t sb = smem_u32(dsm);

    const int tid = threadIdx.x;
    const int lid = tid & 31;
    const int wid = tid >> 5;
    const int wm = wid & 1;
    const int wn = wid >> 1;
    const int bm = blockIdx.y * 128, bn = blockIdx.x * 128;

    const __half* gs[3] = { A + (size_t)bm * K, Wh + (size_t)bn * K, Wl + (size_t)bn * K };

    float acc[4][4][4];
#pragma unroll
    for (int i = 0; i < 4; ++i)
#pragma unroll
        for (int j = 0; j < 4; ++j)
#pragma unroll
            for (int k = 0; k < 4; ++k) acc[i][j][k] = 0.f;

    const int NC = K >> 5;

    auto load_stage = [&](int stage, int kk) {
        const uint32_t stb = sb + (uint32_t)stage * 24576u;
        const int r  = tid >> 1;
        const int k0 = (tid & 1) * 2;
#pragma unroll
        for (int t3 = 0; t3 < 3; ++t3) {
            const uint32_t tb = stb + (uint32_t)t3 * 8192u;
            const __half* g = gs[t3] + kk + (size_t)r * K;
#pragma unroll
            for (int j = 0; j < 2; ++j)
                CP16(tile2_addr(tb, r, k0 + j), (const char*)(g + (k0 + j) * 8));
        }
        CP_COMMIT();
    };

    load_stage(0, 0);
    load_stage(1, 32);

    const int arow = lid & 15;
    const int achd = lid >> 4;

    for (int c = 0; c < NC; ++c) {
        if (c < NC - 1) CP_WAIT1(); else CP_WAIT0();
        __syncthreads();
        if (c + 2 < NC) load_stage((c + 2) % 3, (c + 2) << 5);

        const uint32_t stb = sb + (uint32_t)(c % 3) * 24576u;

#pragma unroll
        for (int ks = 0; ks < 2; ++ks) {
            const int chk = ks * 2 + achd;
            uint32_t af[4][4];
#pragma unroll
            for (int mt = 0; mt < 4; ++mt) {
                const int r = wm * 64 + mt * 16 + arow;
                ldsm4(af[mt], tile2_addr(stb, r, chk));
            }
            uint32_t bh[4][2], bl[4][2];
#pragma unroll
            for (int ntp = 0; ntp < 2; ++ntp) {
                const int r = wn * 32 + ntp * 16 + arow;
                uint32_t t[4], u[4];
                ldsm4(t, tile2_addr(stb + 8192u, r, chk));
                ldsm4(u, tile2_addr(stb + 16384u, r, chk));
                bh[2 * ntp][0] = t[0]; bh[2 * ntp][1] = t[2];
                bh[2 * ntp + 1][0] = t[1]; bh[2 * ntp + 1][1] = t[3];
                bl[2 * ntp][0] = u[0]; bl[2 * ntp][1] = u[2];
                bl[2 * ntp + 1][0] = u[1]; bl[2 * ntp + 1][1] = u[3];
            }
#pragma unroll
            for (int mt = 0; mt < 4; ++mt)
#pragma unroll
                for (int nt = 0; nt < 4; ++nt)
                    mma16816h(acc[mt][nt], af[mt], bh[nt]);
#pragma unroll
            for (int mt = 0; mt < 4; ++mt)
#pragma unroll
                for (int nt = 0; nt < 4; ++nt)
                    mma16816h(acc[mt][nt], af[mt], bl[nt]);
        }
    }

    const int l4 = lid >> 2;
    const int l2 = (lid & 3) * 2;
#pragma unroll
    for (int mt = 0; mt < 4; ++mt) {
#pragma unroll
        for (int nt = 0; nt < 4; ++nt) {
            const int col = bn + wn * 32 + nt * 8 + l2;
#pragma unroll
            for (int half = 0; half < 2; ++half) {
                const int row = bm + wm * 64 + mt * 16 + l4 + half * 8;
                float v0 = acc[mt][nt][2 * half + 0];
                float v1 = acc[mt][nt][2 * half + 1];
                v0 += bias[col]; v1 += bias[col + 1];
                const size_t o = (size_t)row * N + col;
                if (res) { v0 += res[o]; v1 += res[o + 1]; }
                if (relu) { v0 = fmaxf(v0, 0.f); v1 = fmaxf(v1, 0.f); }
                if (C) *(float2*)(C + o) = make_float2(v0, v1);
                if (kd) {
                    if (col >= 2048)
                        *(float2*)(vd + (size_t)row * DD + col - 2048) = make_float2(v0, v1);
                    else if (col >= 1024)
                        *(float2*)(kd + (size_t)row * DD + col - 1024) = make_float2(v0, v1);
                }
                if (Cf) *(uint32_t*)(Cf + o) = pack_h2(v0, v1);
            }
        }
    }
}

// ---------------------------------------------------------------------------
// fp16 1-term GEMM (A single, W single). Used for MLP up and down.
// Stage = A tile (8KB) + W tile (8KB) = 16KB; 3 stages = 48KB smem.
// ---------------------------------------------------------------------------
#define GEMM1_SMEM (3 * 16384)   // 48KB

__global__ __launch_bounds__(256, 2) void gemm_f16_1t(
    const __half* __restrict__ A, const __half* __restrict__ W,
    const float* __restrict__ bias, const float* __restrict__ res,
    float* __restrict__ C, __half* __restrict__ Cf,
    int M, int N, int K, int relu)
{
    extern __shared__ char dsm[];
    const uint32_t sb = smem_u32(dsm);

    const int tid = threadIdx.x;
    const int lid = tid & 31;
    const int wid = tid >> 5;
    const int wm = wid & 1;
    const int wn = wid >> 1;
    const int bm = blockIdx.y * 128, bn = blockIdx.x * 128;

    const __half* gA = A + (size_t)bm * K;
    const __half* gW = W + (size_t)bn * K;

    float acc[4][4][4];
#pragma unroll
    for (int i = 0; i < 4; ++i)
#pragma unroll
        for (int j = 0; j < 4; ++j)
#pragma unroll
            for (int k = 0; k < 4; ++k) acc[i][j][k] = 0.f;

    const int NC = K >> 5;

    auto load_stage = [&](int stage, int kk) {
        const uint32_t stb = sb + (uint32_t)stage * 16384u;
        const int r  = tid >> 1;
        const int k0 = (tid & 1) * 2;
        const __half* ga = gA + kk + (size_t)r * K;
        const __half* gw = gW + kk + (size_t)r * K;
#pragma unroll
        for (int j = 0; j < 2; ++j) {
            CP16(tile2_addr(stb, r, k0 + j),          (const char*)(ga + (k0 + j) * 8));
            CP16(tile2_addr(stb + 8192u, r, k0 + j),  (const char*)(gw + (k0 + j) * 8));
        }
        CP_COMMIT();
    };

    load_stage(0, 0);
    load_stage(1, 32);

    const int arow = lid & 15;
    const int achd = lid >> 4;

    for (int c = 0; c < NC; ++c) {
        if (c < NC - 1) CP_WAIT1(); else CP_WAIT0();
        __syncthreads();
        if (c + 2 < NC) load_stage((c + 2) % 3, (c + 2) << 5);

        const uint32_t stb = sb + (uint32_t)(c % 3) * 16384u;

#pragma unroll
        for (int ks = 0; ks < 2; ++ks) {
            const int chk = ks * 2 + achd;
            uint32_t af[4][4];
#pragma unroll
            for (int mt = 0; mt < 4; ++mt) {
                const int r = wm * 64 + mt * 16 + arow;
                ldsm4(af[mt], tile2_addr(stb, r, chk));
            }
            uint32_t bf[4][2];
#pragma unroll
            for (int ntp = 0; ntp < 2; ++ntp) {
                const int r = wn * 32 + ntp * 16 + arow;
                uint32_t t[4];
                ldsm4(t, tile2_addr(stb + 8192u, r, chk));
                bf[2 * ntp][0] = t[0]; bf[2 * ntp][1] = t[2];
                bf[2 * ntp + 1][0] = t[1]; bf[2 * ntp + 1][1] = t[3];
            }
#pragma unroll
            for (int mt = 0; mt < 4; ++mt)
#pragma unroll
                for (int nt = 0; nt < 4; ++nt)
                    mma16816h(acc[mt][nt], af[mt], bf[nt]);
        }
    }

    const int l4 = lid >> 2;
    const int l2 = (lid & 3) * 2;
#pragma unroll
    for (int mt = 0; mt < 4; ++mt) {
#pragma unroll
        for (int nt = 0; nt < 4; ++nt) {
            const int col = bn + wn * 32 + nt * 8 + l2;
#pragma unroll
            for (int half = 0; half < 2; ++half) {
                const int row = bm + wm * 64 + mt * 16 + l4 + half * 8;
                float v0 = acc[mt][nt][2 * half + 0];
                float v1 = acc[mt][nt][2 * half + 1];
                v0 += bias[col]; v1 += bias[col + 1];
                const size_t o = (size_t)row * N + col;
                if (res) { v0 += res[o]; v1 += res[o + 1]; }
                if (relu) { v0 = fmaxf(v0, 0.f); v1 = fmaxf(v1, 0.f); }
                if (C) *(float2*)(C + o) = make_float2(v0, v1);
                if (Cf) *(uint32_t*)(Cf + o) = pack_h2(v0, v1);
            }
        }
    }
}

// ---------------------------------------------------------------------------
// fp32 -> fp16 hi/lo split and fp32 -> fp16 single
// ---------------------------------------------------------------------------
__global__ __launch_bounds__(256) void cvt_f16_hilo_k(
    const float4* __restrict__ in, uint32_t* __restrict__ hi,
    uint32_t* __restrict__ lo, int n4)
{
    int i = blockIdx.x * blockDim.x + threadIdx.x;
    if (i >= n4) return;
    float4 v = in[i];
    hi[2 * i]     = pack_h2(v.x, v.y);
    hi[2 * i + 1] = pack_h2(v.z, v.w);
    lo[2 * i]     = pack_h2lo(v.x, v.y);
    lo[2 * i + 1] = pack_h2lo(v.z, v.w);
}
__global__ __launch_bounds__(256) void cvt_f16_k(
    const float4* __restrict__ in, uint32_t* __restrict__ o, int n4)
{
    int i = blockIdx.x * blockDim.x + threadIdx.x;
    if (i >= n4) return;
    float4 v = in[i];
    o[2 * i]     = pack_h2(v.x, v.y);
    o[2 * i + 1] = pack_h2(v.z, v.w);
}

// ---------------------------------------------------------------------------
// fp16 1-term flash attention, causal, online softmax.
// Q, K, V all single fp16. Smem: Q 16KB + 3 x (K 8KB + V 8KB) = 64KB.
// 2 CTAs/SM. One sync per KV block; heavy q-tiles first.
// ---------------------------------------------------------------------------
#define FA_SMEM (16384 + 3 * 16384)   // 64KB

__global__ __launch_bounds__(256, 2) void flash_f16_k(
    const __half* __restrict__ qkv, __half* __restrict__ out)
{
    extern __shared__ char dsm[];
    const uint32_t sb = smem_u32(dsm);
    const uint32_t Qt = sb;

    const int tid = threadIdx.x;
    const int lid = tid & 31;
    const int w   = tid >> 5;
    const int q0  = (gridDim.x - 1 - blockIdx.x) * 128;   // heavy tiles first
    const int b   = blockIdx.y >> 4;
    const int h   = blockIdx.y & 15;
    const size_t grow = (size_t)(b * SS);

    auto load_q = [&]() {
        const int row = tid >> 1;
        const int cb  = (tid & 1) * 4;
        const size_t src = (grow + q0 + row) * 3072 + h * HD;
#pragma unroll
        for (int j = 0; j < 4; ++j) {
            const int ch = cb + j;
            CP16(tile_addr(Qt, row, ch), (const char*)(qkv + src + ch * 8));
        }
    };
    auto load_kv = [&](int buf, int k0) {
        const uint32_t bbase = sb + 16384u + (uint32_t)buf * 16384u;
        const int row = tid >> 2;
        const int cb  = (tid & 3) * 2;
        const size_t srcK = (grow + k0 + row) * 3072 + 1024 + h * HD;
        const size_t srcV = srcK + 1024;
#pragma unroll
        for (int j = 0; j < 2; ++j) {
            const int ch = cb + j;
            const uint32_t off = tile_addr(0, row, ch);
            CP16(bbase + off,          (const char*)(qkv + srcK + ch * 8));
            CP16(bbase + 8192u + off,  (const char*)(qkv + srcV + ch * 8));
        }
    };

    const int nblk = q0 / 64 + 2;

    load_q();
    load_kv(0, 0);
    CP_COMMIT();
    load_kv(1, 64);
    CP_COMMIT();

    const int arow = lid & 15;
    const int achd = lid >> 4;

    uint32_t qf[4][4];
    float of[8][4];
#pragma unroll
    for (int i = 0; i < 8; ++i)
#pragma unroll
        for (int j = 0; j < 4; ++j) of[i][j] = 0.f;
    float m0 = -1e30f, m1 = -1e30f, l0 = 0.f, l1 = 0.f;

    const int row_lo = lid >> 2;

    for (int c = 0; c < nblk; ++c) {
        if (c < nblk - 1) CP_WAIT1(); else CP_WAIT0();
        __syncthreads();
        if (c + 2 < nblk) { load_kv((c + 2) % 3, (c + 2) * 64); CP_COMMIT(); }

        if (c == 0) {
#pragma unroll
            for (int ks = 0; ks < 4; ++ks)
                ldsm4(qf[ks], tile_addr(Qt, w * 16 + arow, ks * 2 + achd));
        }

        const uint32_t kb = sb + 16384u + (uint32_t)(c % 3) * 16384u;
        const int k0 = c * 64;

        float sf[8][4];
#pragma unroll
        for (int i = 0; i < 8; ++i)
#pragma unroll
            for (int j = 0; j < 4; ++j) sf[i][j] = 0.f;

#pragma unroll
        for (int ks = 0; ks < 4; ++ks) {
            uint32_t bh[8][2];
#pragma unroll
            for (int ntp = 0; ntp < 4; ++ntp) {
                uint32_t t[4];
                ldsm4(t, tile_addr(kb, ntp * 16 + arow, ks * 2 + achd));
                bh[2 * ntp][0] = t[0]; bh[2 * ntp][1] = t[2];
                bh[2 * ntp + 1][0] = t[1]; bh[2 * ntp + 1][1] = t[3];
            }
#pragma unroll
            for (int nt = 0; nt < 8; ++nt) mma16816h(sf[nt], qf[ks], bh[nt]);
        }

        const int grow0 = q0 + w * 16 + row_lo;
        const int grow1 = grow0 + 8;
        const bool need_mask = (k0 + 63 > q0 + w * 16);
#pragma unroll
        for (int nt = 0; nt < 8; ++nt) {
            const int col = k0 + nt * 8 + 2 * (lid & 3);
#pragma unroll
            for (int j = 0; j < 4; ++j) sf[nt][j] *= 0.125f;
            if (need_mask) {
                if (col     > grow0) sf[nt][0] = -1e30f;
                if (col + 1 > grow0) sf[nt][1] = -1e30f;
                if (col     > grow1) sf[nt][2] = -1e30f;
                if (col + 1 > grow1) sf[nt][3] = -1e30f;
            }
        }

        float tm0 = -1e30f, tm1 = -1e30f;
#pragma unroll
        for (int nt = 0; nt < 8; ++nt) {
            tm0 = fmaxf(tm0, fmaxf(sf[nt][0], sf[nt][1]));
            tm1 = fmaxf(tm1, fmaxf(sf[nt][2], sf[nt][3]));
        }
        tm0 = fmaxf(tm0, __shfl_xor_sync(0xffffffffu, tm0, 1));
        tm0 = fmaxf(tm0, __shfl_xor_sync(0xffffffffu, tm0, 2));
        tm1 = fmaxf(tm1, __shfl_xor_sync(0xffffffffu, tm1, 1));
        tm1 = fmaxf(tm1, __shfl_xor_sync(0xffffffffu, tm1, 2));

        const float mn0 = fmaxf(m0, tm0), mn1 = fmaxf(m1, tm1);
        const float cr0 = __expf(m0 - mn0), cr1 = __expf(m1 - mn1);
        m0 = mn0; m1 = mn1;

        float ps0 = 0.f, ps1 = 0.f;
#pragma unroll
        for (int nt = 0; nt < 8; ++nt) {
            sf[nt][0] = __expf(sf[nt][0] - mn0);
            sf[nt][1] = __expf(sf[nt][1] - mn0);
            sf[nt][2] = __expf(sf[nt][2] - mn1);
            sf[nt][3] = __expf(sf[nt][3] - mn1);
            ps0 += sf[nt][0] + sf[nt][1];
            ps1 += sf[nt][2] + sf[nt][3];
        }
        ps0 += __shfl_xor_sync(0xffffffffu, ps0, 1);
        ps0 += __shfl_xor_sync(0xffffffffu, ps0, 2);
        ps1 += __shfl_xor_sync(0xffffffffu, ps1, 1);
        ps1 += __shfl_xor_sync(0xffffffffu, ps1, 2);
        l0 = l0 * cr0 + ps0;
        l1 = l1 * cr1 + ps1;
#pragma unroll
        for (int nt = 0; nt < 8; ++nt) {
            of[nt][0] *= cr0; of[nt][1] *= cr0;
            of[nt][2] *= cr1; of[nt][3] *= cr1;
        }

        uint32_t pa[4][4];
#pragma unroll
        for (int kk = 0; kk < 4; ++kk) {
            pa[kk][0] = pack_h2(sf[2 * kk][0], sf[2 * kk][1]);
            pa[kk][1] = pack_h2(sf[2 * kk][2], sf[2 * kk][3]);
            pa[kk][2] = pack_h2(sf[2 * kk + 1][0], sf[2 * kk + 1][1]);
            pa[kk][3] = pack_h2(sf[2 * kk + 1][2], sf[2 * kk + 1][3]);
        }

        const uint32_t vb = kb + 8192u;
#pragma unroll
        for (int ks = 0; ks < 4; ++ks) {
            uint32_t vh[8][2];
#pragma unroll
            for (int ntp = 0; ntp < 4; ++ntp) {
                const int krow = ks * 16 + arow;
                uint32_t t[4];
                ldsm4t(t, tile_addr(vb, krow, ntp * 2 + achd));
                vh[2 * ntp][0] = t[0]; vh[2 * ntp][1] = t[1];
                vh[2 * ntp + 1][0] = t[2]; vh[2 * ntp + 1][1] = t[3];
            }
#pragma unroll
            for (int nt = 0; nt < 8; ++nt) mma16816h(of[nt], pa[ks], vh[nt]);
        }
    }

    const float iv0 = 1.0f / l0, iv1 = 1.0f / l1;
    const size_t r0 = (grow + q0 + w * 16 + row_lo) * DD + h * HD;
    const size_t r1 = r0 + 8 * DD;
#pragma unroll
    for (int nt = 0; nt < 8; ++nt) {
        const int cofs = nt * 8 + 2 * (lid & 3);
        *(uint32_t*)(out + r0 + cofs) = pack_h2(of[nt][0] * iv0, of[nt][1] * iv0);
        *(uint32_t*)(out + r1 + cofs) = pack_h2(of[nt][2] * iv1, of[nt][3] * iv1);
    }
}

// ---------------------------------------------------------------------------
// LayerNorm over D=1024; optional fused fp16 single output
// ---------------------------------------------------------------------------
__global__ __launch_bounds__(256) void layernorm_k(
    const float* __restrict__ in, const float* __restrict__ w,
    const float* __restrict__ b, float* __restrict__ out,
    __half* __restrict__ of16)
{
    __shared__ float red[8];
    __shared__ float bval;
    const int tid = threadIdx.x;
    const size_t base = (size_t)blockIdx.x * DD;

    float4 v = ((const float4*)(in + base))[tid];
    float s = v.x + v.y + v.z + v.w;
#pragma unroll
    for (int off = 16; off; off >>= 1) s += __shfl_xor_sync(0xffffffffu, s, off);
    if ((tid & 31) == 0) red[tid >> 5] = s;
    __syncthreads();
    if (tid == 0) {
        float t = 0.f;
#pragma unroll
        for (int i = 0; i < 8; ++i) t += red[i];
        bval = t * (1.0f / DD);
    }
    __syncthreads();
    const float mu = bval;
    __syncthreads();

    float dx = v.x - mu, dy = v.y - mu, dz = v.z - mu, dw = v.w - mu;
    float q = dx * dx + dy * dy + dz * dz + dw * dw;
#pragma unroll
    for (int off = 16; off; off >>= 1) q += __shfl_xor_sync(0xffffffffu, q, off);
    if ((tid & 31) == 0) red[tid >> 5] = q;
    __syncthreads();
    if (tid == 0) {
        float t = 0.f;
#pragma unroll
        for (int i = 0; i < 8; ++i) t += red[i];
        bval = t * (1.0f / DD);
    }
    __syncthreads();
    const float inv = rsqrtf(bval + 1e-5f);

    float4 w4 = ((const float4*)w)[tid];
    float4 b4 = ((const float4*)b)[tid];
    float4 r = make_float4(dx * inv * w4.x + b4.x,
                           dy * inv * w4.y + b4.y,
                           dz * inv * w4.z + b4.z,
                           dw * inv * w4.w + b4.w);
    ((float4*)(out + base))[tid] = r;
    if (of16) {
        *(uint32_t*)(of16 + base + 4 * tid)     = pack_h2(r.x, r.y);
        *(uint32_t*)(of16 + base + 4 * tid + 2) = pack_h2(r.z, r.w);
    }
}

// ---------------------------------------------------------------------------
// Launch
// ---------------------------------------------------------------------------
static inline void cvtf2(const float* in, __half* hi, __half* lo, size_t n) {
    int n4 = (int)(n / 4);
    cvt_f16_hilo_k<<<(n4 + 255) / 256, 256>>>((const float4*)in,
                                              (uint32_t*)hi, (uint32_t*)lo, n4);
}
static inline void cvtf1(const float* in, __half* o, size_t n) {
    int n4 = (int)(n / 4);
    cvt_f16_k<<<(n4 + 255) / 256, 256>>>((const float4*)in, (uint32_t*)o, n4);
}

extern "C" void kernel_launch(void* const* d_in, const int* in_sizes, int n_in,
                              void* d_out, int out_size)
{
    const float* x     = (const float*)d_in[0];
    const float* qkv_w = (const float*)d_in[1];
    const float* qkv_b = (const float*)d_in[2];
    const float* out_w = (const float*)d_in[3];
    const float* out_b = (const float*)d_in[4];
    const float* w1    = (const float*)d_in[5];
    const float* b1    = (const float*)d_in[6];
    const float* w2    = (const float*)d_in[7];
    const float* b2    = (const float*)d_in[8];
    const float* ln1w  = (const float*)d_in[9];
    const float* ln1b  = (const float*)d_in[10];
    const float* ln2w  = (const float*)d_in[11];
    const float* ln2b  = (const float*)d_in[12];

    float* outp = (float*)d_out;
    float* kdst = outp + (size_t)MTOK * DD;
    float* vdst = outp + (size_t)2 * MTOK * DD;

    float *h1pre, *h1, *h2pre;
    __half *qkvf, *af, *h1f, *midf, *xf;
    __half *wqhf, *wqlf, *owhf, *owlf, *w1f, *w2f;
    cudaGetSymbolAddress((void**)&qkvf,  g_qkvf);
    cudaGetSymbolAddress((void**)&af,    g_af);
    cudaGetSymbolAddress((void**)&h1pre, g_h1pre);
    cudaGetSymbolAddress((void**)&h1,    g_h1);
    cudaGetSymbolAddress((void**)&h2pre, g_h2pre);
    cudaGetSymbolAddress((void**)&h1f,   g_h1f);
    cudaGetSymbolAddress((void**)&midf,  g_midf);
    cudaGetSymbolAddress((void**)&xf,    g_xf);
    cudaGetSymbolAddress((void**)&wqhf,  g_wqhf); cudaGetSymbolAddress((void**)&wqlf, g_wqlf);
    cudaGetSymbolAddress((void**)&owhf,  g_owhf); cudaGetSymbolAddress((void**)&owlf, g_owlf);
    cudaGetSymbolAddress((void**)&w1f,   g_w1f);
    cudaGetSymbolAddress((void**)&w2f,   g_w2f);

    cudaFuncSetAttribute(gemm_f16_2t,
                         cudaFuncAttributeMaxDynamicSharedMemorySize, GEMMF_SMEM);
    cudaFuncSetAttribute(gemm_f16_1t,
                         cudaFuncAttributeMaxDynamicSharedMemorySize, GEMM1_SMEM);
    cudaFuncSetAttribute(flash_f16_k,
                         cudaFuncAttributeMaxDynamicSharedMemorySize, FA_SMEM);

    // 0) weight splits / conversions
    cvtf2(qkv_w, wqhf, wqlf, (size_t)3 * DD * DD);
    cvtf2(out_w, owhf, owlf, (size_t)DD * DD);
    cvtf1(w1, w1f, (size_t)FF_DIM * DD);
    cvtf1(w2, w2f, (size_t)DD * FF_DIM);
    cvtf1(x,  xf,  (size_t)MTOK * DD);

    // 1) QKV projection (fp16 2-term) -> qkv fp16 single; k/v fp32 to d_out
    gemm_f16_2t<<<dim3(3072 / 128, MTOK / 128), 256, GEMMF_SMEM>>>(
        xf, wqhf, wqlf, qkv_b, nullptr, nullptr, qkvf, kdst, vdst,
        MTOK, 3 * DD, DD, 0);
    // 2) flash attention (fp16 1-term) -> attn fp16 single
    flash_f16_k<<<dim3(SS / 128, BB * HH), 256, FA_SMEM>>>(qkvf, af);
    // 3) out projection (fp16 2-term) + residual x -> h1pre
    gemm_f16_2t<<<dim3(DD / 128, MTOK / 128), 256, GEMMF_SMEM>>>(
        af, owhf, owlf, out_b, x, h1pre, nullptr, nullptr, nullptr,
        MTOK, DD, DD, 0);
    // 4) LN1 -> h1 fp32 + h1f fp16
    layernorm_k<<<MTOK, 256>>>(h1pre, ln1w, ln1b, h1, h1f);
    // 5) MLP up (fp16 1-term) + ReLU -> midf fp16
    gemm_f16_1t<<<dim3(FF_DIM / 128, MTOK / 128), 256, GEMM1_SMEM>>>(
        h1f, w1f, b1, nullptr, nullptr, midf,
        MTOK, FF_DIM, DD, 1);
    // 6) MLP down (fp16 1-term) + residual h1 -> h2pre fp32
    gemm_f16_1t<<<dim3(DD / 128, MTOK / 128), 256, GEMM1_SMEM>>>(
        midf, w2f, b2, h1, h2pre, nullptr,
        MTOK, DD, FF_DIM, 0);
    // 7) LN2 -> out
    layernorm_k<<<MTOK, 256>>>(h2pre, ln2w, ln2b, outp, nullptr);
}

// round 11
// speedup vs baseline: 2.4352x; 1.1810x over previous
#include <cuda_runtime.h>
#include <cuda_fp16.h>
#include <cstdint>

// Problem constants: B=2, S=2048, D=1024, H=16, hd=64, FF=4096
#define BB 2
#define SS 2048
#define DD 1024
#define HH 16
#define HD 64
#define FF_DIM 4096
#define MTOK (BB*SS)          // 4096 rows

// ---------------------------------------------------------------------------
// Scratch (device globals; no allocation allowed)
// ---------------------------------------------------------------------------
__device__ __half g_qkvf[(size_t)MTOK * 3 * DD];   // qkv, fp16 single
__device__ __half g_af[(size_t)MTOK * DD];         // attn out, fp16 single
__device__ float  g_h1pre[(size_t)MTOK * DD];
__device__ float  g_h1[(size_t)MTOK * DD];
__device__ float  g_h2pre[(size_t)MTOK * DD];
__device__ __half g_h1f[(size_t)MTOK * DD];
__device__ __half g_midf[(size_t)MTOK * FF_DIM];
__device__ __half g_xf[(size_t)MTOK * DD];
__device__ __half g_wqf[(size_t)3 * DD * DD];
__device__ __half g_owf[(size_t)DD * DD];
__device__ __half g_w1f[(size_t)FF_DIM * DD];
__device__ __half g_w2f[(size_t)DD * FF_DIM];

// ---------------------------------------------------------------------------
// MMA / ldmatrix / cp.async helpers
// ---------------------------------------------------------------------------
__device__ __forceinline__ uint32_t smem_u32(const void* p) {
    uint32_t a;
    asm("{ .reg .u64 t; cvta.to.shared.u64 t, %1; cvt.u32.u64 %0, t; }"
        : "=r"(a) : "l"(p));
    return a;
}
__device__ __forceinline__ void ldsm4(uint32_t* r, uint32_t a) {
    asm volatile("ldmatrix.sync.aligned.m8n8.x4.shared.b16 {%0,%1,%2,%3}, [%4];"
                 : "=r"(r[0]), "=r"(r[1]), "=r"(r[2]), "=r"(r[3]) : "r"(a));
}
__device__ __forceinline__ void ldsm4t(uint32_t* r, uint32_t a) {
    asm volatile("ldmatrix.sync.aligned.m8n8.x4.trans.shared.b16 {%0,%1,%2,%3}, [%4];"
                 : "=r"(r[0]), "=r"(r[1]), "=r"(r[2]), "=r"(r[3]) : "r"(a));
}
__device__ __forceinline__ void mma16816h(float* c, const uint32_t* a, const uint32_t* b) {
    asm volatile(
        "mma.sync.aligned.m16n8k16.row.col.f32.f16.f16.f32 "
        "{%0,%1,%2,%3}, {%4,%5,%6,%7}, {%8,%9}, {%0,%1,%2,%3};"
        : "+f"(c[0]), "+f"(c[1]), "+f"(c[2]), "+f"(c[3])
        : "r"(a[0]), "r"(a[1]), "r"(a[2]), "r"(a[3]), "r"(b[0]), "r"(b[1]));
}
#define CP16(dst, src) \
    asm volatile("cp.async.cg.shared.global [%0], [%1], 16;" :: "r"(dst), "l"(src) : "memory")
#define CP_COMMIT() asm volatile("cp.async.commit_group;" ::: "memory")
#define CP_WAIT1()  asm volatile("cp.async.wait_group 1;" ::: "memory")
#define CP_WAIT0()  asm volatile("cp.async.wait_group 0;" ::: "memory")

// 128B-row tile (flash): row stride 128B, chunk ch swizzled by row&7.
__device__ __forceinline__ uint32_t tile_addr(uint32_t base, int row, int ch) {
    return base + (uint32_t)row * 128u + (uint32_t)((ch ^ (row & 7)) << 4);
}
// paired-row tile (gemm): [128][32] 16-bit elems in 64 smem rows of 128B.
__device__ __forceinline__ uint32_t tile2_addr(uint32_t base, int r, int k) {
    const int s = r >> 1;
    const int c = ((r & 1) << 2) | k;
    return base + (uint32_t)s * 128u + (uint32_t)((c ^ (s & 7)) << 4);
}
__device__ __forceinline__ uint32_t pack_h2(float a, float b) {
    __half2 h = __halves2half2(__float2half(a), __float2half(b));
    return *(uint32_t*)&h;
}

// ---------------------------------------------------------------------------
// fp16 1-term GEMM (A single, W single). Used for ALL projections.
// Stage = A tile (8KB) + W tile (8KB) = 16KB; 3 stages = 48KB smem.
// Optional outputs: fp32 C, fp16 Cf, fused fp32 kv-cache split (QKV mode).
// ---------------------------------------------------------------------------
#define GEMM1_SMEM (3 * 16384)   // 48KB

__global__ __launch_bounds__(256, 2) void gemm_f16_1t(
    const __half* __restrict__ A, const __half* __restrict__ W,
    const float* __restrict__ bias, const float* __restrict__ res,
    float* __restrict__ C, __half* __restrict__ Cf,
    float* __restrict__ kd, float* __restrict__ vd,
    int M, int N, int K, int relu)
{
    extern __shared__ char dsm[];
    const uint32_t sb = smem_u32(dsm);

    const int tid = threadIdx.x;
    const int lid = tid & 31;
    const int wid = tid >> 5;
    const int wm = wid & 1;
    const int wn = wid >> 1;
    const int bm = blockIdx.y * 128, bn = blockIdx.x * 128;

    const __half* gA = A + (size_t)bm * K;
    const __half* gW = W + (size_t)bn * K;

    float acc[4][4][4];
#pragma unroll
    for (int i = 0; i < 4; ++i)
#pragma unroll
        for (int j = 0; j < 4; ++j)
#pragma unroll
            for (int k = 0; k < 4; ++k) acc[i][j][k] = 0.f;

    const int NC = K >> 5;

    auto load_stage = [&](int stage, int kk) {
        const uint32_t stb = sb + (uint32_t)stage * 16384u;
        const int r  = tid >> 1;
        const int k0 = (tid & 1) * 2;
        const __half* ga = gA + kk + (size_t)r * K;
        const __half* gw = gW + kk + (size_t)r * K;
#pragma unroll
        for (int j = 0; j < 2; ++j) {
            CP16(tile2_addr(stb, r, k0 + j),          (const char*)(ga + (k0 + j) * 8));
            CP16(tile2_addr(stb + 8192u, r, k0 + j),  (const char*)(gw + (k0 + j) * 8));
        }
        CP_COMMIT();
    };

    load_stage(0, 0);
    load_stage(1, 32);

    const int arow = lid & 15;
    const int achd = lid >> 4;

    for (int c = 0; c < NC; ++c) {
        if (c < NC - 1) CP_WAIT1(); else CP_WAIT0();
        __syncthreads();
        if (c + 2 < NC) load_stage((c + 2) % 3, (c + 2) << 5);

        const uint32_t stb = sb + (uint32_t)(c % 3) * 16384u;

#pragma unroll
        for (int ks = 0; ks < 2; ++ks) {
            const int chk = ks * 2 + achd;
            uint32_t af[4][4];
#pragma unroll
            for (int mt = 0; mt < 4; ++mt) {
                const int r = wm * 64 + mt * 16 + arow;
                ldsm4(af[mt], tile2_addr(stb, r, chk));
            }
            uint32_t bf[4][2];
#pragma unroll
            for (int ntp = 0; ntp < 2; ++ntp) {
                const int r = wn * 32 + ntp * 16 + arow;
                uint32_t t[4];
                ldsm4(t, tile2_addr(stb + 8192u, r, chk));
                bf[2 * ntp][0] = t[0]; bf[2 * ntp][1] = t[2];
                bf[2 * ntp + 1][0] = t[1]; bf[2 * ntp + 1][1] = t[3];
            }
#pragma unroll
            for (int mt = 0; mt < 4; ++mt)
#pragma unroll
                for (int nt = 0; nt < 4; ++nt)
                    mma16816h(acc[mt][nt], af[mt], bf[nt]);
        }
    }

    const int l4 = lid >> 2;
    const int l2 = (lid & 3) * 2;
#pragma unroll
    for (int mt = 0; mt < 4; ++mt) {
#pragma unroll
        for (int nt = 0; nt < 4; ++nt) {
            const int col = bn + wn * 32 + nt * 8 + l2;
#pragma unroll
            for (int half = 0; half < 2; ++half) {
                const int row = bm + wm * 64 + mt * 16 + l4 + half * 8;
                float v0 = acc[mt][nt][2 * half + 0];
                float v1 = acc[mt][nt][2 * half + 1];
                v0 += bias[col]; v1 += bias[col + 1];
                const size_t o = (size_t)row * N + col;
                if (res) { v0 += res[o]; v1 += res[o + 1]; }
                if (relu) { v0 = fmaxf(v0, 0.f); v1 = fmaxf(v1, 0.f); }
                if (C) *(float2*)(C + o) = make_float2(v0, v1);
                if (kd) {
                    if (col >= 2048)
                        *(float2*)(vd + (size_t)row * DD + col - 2048) = make_float2(v0, v1);
                    else if (col >= 1024)
                        *(float2*)(kd + (size_t)row * DD + col - 1024) = make_float2(v0, v1);
                }
                if (Cf) *(uint32_t*)(Cf + o) = pack_h2(v0, v1);
            }
        }
    }
}

// ---------------------------------------------------------------------------
// fp32 -> fp16 single
// ---------------------------------------------------------------------------
__global__ __launch_bounds__(256) void cvt_f16_k(
    const float4* __restrict__ in, uint32_t* __restrict__ o, int n4)
{
    int i = blockIdx.x * blockDim.x + threadIdx.x;
    if (i >= n4) return;
    float4 v = in[i];
    o[2 * i]     = pack_h2(v.x, v.y);
    o[2 * i + 1] = pack_h2(v.z, v.w);
}

// ---------------------------------------------------------------------------
// fp16 1-term flash attention, causal, online softmax.
// Q, K, V all single fp16. Smem: Q 16KB + 3 x (K 8KB + V 8KB) = 64KB.
// 2 CTAs/SM. One sync per KV block; heavy q-tiles first.
// ---------------------------------------------------------------------------
#define FA_SMEM (16384 + 3 * 16384)   // 64KB

__global__ __launch_bounds__(256, 2) void flash_f16_k(
    const __half* __restrict__ qkv, __half* __restrict__ out)
{
    extern __shared__ char dsm[];
    const uint32_t sb = smem_u32(dsm);
    const uint32_t Qt = sb;

    const int tid = threadIdx.x;
    const int lid = tid & 31;
    const int w   = tid >> 5;
    const int q0  = (gridDim.x - 1 - blockIdx.x) * 128;   // heavy tiles first
    const int b   = blockIdx.y >> 4;
    const int h   = blockIdx.y & 15;
    const size_t grow = (size_t)(b * SS);

    auto load_q = [&]() {
        const int row = tid >> 1;
        const int cb  = (tid & 1) * 4;
        const size_t src = (grow + q0 + row) * 3072 + h * HD;
#pragma unroll
        for (int j = 0; j < 4; ++j) {
            const int ch = cb + j;
            CP16(tile_addr(Qt, row, ch), (const char*)(qkv + src + ch * 8));
        }
    };
    auto load_kv = [&](int buf, int k0) {
        const uint32_t bbase = sb + 16384u + (uint32_t)buf * 16384u;
        const int row = tid >> 2;
        const int cb  = (tid & 3) * 2;
        const size_t srcK = (grow + k0 + row) * 3072 + 1024 + h * HD;
        const size_t srcV = srcK + 1024;
#pragma unroll
        for (int j = 0; j < 2; ++j) {
            const int ch = cb + j;
            const uint32_t off = tile_addr(0, row, ch);
            CP16(bbase + off,          (const char*)(qkv + srcK + ch * 8));
            CP16(bbase + 8192u + off,  (const char*)(qkv + srcV + ch * 8));
        }
    };

    const int nblk = q0 / 64 + 2;

    load_q();
    load_kv(0, 0);
    CP_COMMIT();
    load_kv(1, 64);
    CP_COMMIT();

    const int arow = lid & 15;
    const int achd = lid >> 4;

    uint32_t qf[4][4];
    float of[8][4];
#pragma unroll
    for (int i = 0; i < 8; ++i)
#pragma unroll
        for (int j = 0; j < 4; ++j) of[i][j] = 0.f;
    float m0 = -1e30f, m1 = -1e30f, l0 = 0.f, l1 = 0.f;

    const int row_lo = lid >> 2;

    for (int c = 0; c < nblk; ++c) {
        if (c < nblk - 1) CP_WAIT1(); else CP_WAIT0();
        __syncthreads();
        if (c + 2 < nblk) { load_kv((c + 2) % 3, (c + 2) * 64); CP_COMMIT(); }

        if (c == 0) {
#pragma unroll
            for (int ks = 0; ks < 4; ++ks)
                ldsm4(qf[ks], tile_addr(Qt, w * 16 + arow, ks * 2 + achd));
        }

        const uint32_t kb = sb + 16384u + (uint32_t)(c % 3) * 16384u;
        const int k0 = c * 64;

        float sf[8][4];
#pragma unroll
        for (int i = 0; i < 8; ++i)
#pragma unroll
            for (int j = 0; j < 4; ++j) sf[i][j] = 0.f;

#pragma unroll
        for (int ks = 0; ks < 4; ++ks) {
            uint32_t bh[8][2];
#pragma unroll
            for (int ntp = 0; ntp < 4; ++ntp) {
                uint32_t t[4];
                ldsm4(t, tile_addr(kb, ntp * 16 + arow, ks * 2 + achd));
                bh[2 * ntp][0] = t[0]; bh[2 * ntp][1] = t[2];
                bh[2 * ntp + 1][0] = t[1]; bh[2 * ntp + 1][1] = t[3];
            }
#pragma unroll
            for (int nt = 0; nt < 8; ++nt) mma16816h(sf[nt], qf[ks], bh[nt]);
        }

        const int grow0 = q0 + w * 16 + row_lo;
        const int grow1 = grow0 + 8;
        const bool need_mask = (k0 + 63 > q0 + w * 16);
#pragma unroll
        for (int nt = 0; nt < 8; ++nt) {
            const int col = k0 + nt * 8 + 2 * (lid & 3);
#pragma unroll
            for (int j = 0; j < 4; ++j) sf[nt][j] *= 0.125f;
            if (need_mask) {
                if (col     > grow0) sf[nt][0] = -1e30f;
                if (col + 1 > grow0) sf[nt][1] = -1e30f;
                if (col     > grow1) sf[nt][2] = -1e30f;
                if (col + 1 > grow1) sf[nt][3] = -1e30f;
            }
        }

        float tm0 = -1e30f, tm1 = -1e30f;
#pragma unroll
        for (int nt = 0; nt < 8; ++nt) {
            tm0 = fmaxf(tm0, fmaxf(sf[nt][0], sf[nt][1]));
            tm1 = fmaxf(tm1, fmaxf(sf[nt][2], sf[nt][3]));
        }
        tm0 = fmaxf(tm0, __shfl_xor_sync(0xffffffffu, tm0, 1));
        tm0 = fmaxf(tm0, __shfl_xor_sync(0xffffffffu, tm0, 2));
        tm1 = fmaxf(tm1, __shfl_xor_sync(0xffffffffu, tm1, 1));
        tm1 = fmaxf(tm1, __shfl_xor_sync(0xffffffffu, tm1, 2));

        const float mn0 = fmaxf(m0, tm0), mn1 = fmaxf(m1, tm1);
        const float cr0 = __expf(m0 - mn0), cr1 = __expf(m1 - mn1);
        m0 = mn0; m1 = mn1;

        float ps0 = 0.f, ps1 = 0.f;
#pragma unroll
        for (int nt = 0; nt < 8; ++nt) {
            sf[nt][0] = __expf(sf[nt][0] - mn0);
            sf[nt][1] = __expf(sf[nt][1] - mn0);
            sf[nt][2] = __expf(sf[nt][2] - mn1);
            sf[nt][3] = __expf(sf[nt][3] - mn1);
            ps0 += sf[nt][0] + sf[nt][1];
            ps1 += sf[nt][2] + sf[nt][3];
        }
        ps0 += __shfl_xor_sync(0xffffffffu, ps0, 1);
        ps0 += __shfl_xor_sync(0xffffffffu, ps0, 2);
        ps1 += __shfl_xor_sync(0xffffffffu, ps1, 1);
        ps1 += __shfl_xor_sync(0xffffffffu, ps1, 2);
        l0 = l0 * cr0 + ps0;
        l1 = l1 * cr1 + ps1;
#pragma unroll
        for (int nt = 0; nt < 8; ++nt) {
            of[nt][0] *= cr0; of[nt][1] *= cr0;
            of[nt][2] *= cr1; of[nt][3] *= cr1;
        }

        uint32_t pa[4][4];
#pragma unroll
        for (int kk = 0; kk < 4; ++kk) {
            pa[kk][0] = pack_h2(sf[2 * kk][0], sf[2 * kk][1]);
            pa[kk][1] = pack_h2(sf[2 * kk][2], sf[2 * kk][3]);
            pa[kk][2] = pack_h2(sf[2 * kk + 1][0], sf[2 * kk + 1][1]);
            pa[kk][3] = pack_h2(sf[2 * kk + 1][2], sf[2 * kk + 1][3]);
        }

        const uint32_t vb = kb + 8192u;
#pragma unroll
        for (int ks = 0; ks < 4; ++ks) {
            uint32_t vh[8][2];
#pragma unroll
            for (int ntp = 0; ntp < 4; ++ntp) {
                const int krow = ks * 16 + arow;
                uint32_t t[4];
                ldsm4t(t, tile_addr(vb, krow, ntp * 2 + achd));
                vh[2 * ntp][0] = t[0]; vh[2 * ntp][1] = t[1];
                vh[2 * ntp + 1][0] = t[2]; vh[2 * ntp + 1][1] = t[3];
            }
#pragma unroll
            for (int nt = 0; nt < 8; ++nt) mma16816h(of[nt], pa[ks], vh[nt]);
        }
    }

    const float iv0 = 1.0f / l0, iv1 = 1.0f / l1;
    const size_t r0 = (grow + q0 + w * 16 + row_lo) * DD + h * HD;
    const size_t r1 = r0 + 8 * DD;
#pragma unroll
    for (int nt = 0; nt < 8; ++nt) {
        const int cofs = nt * 8 + 2 * (lid & 3);
        *(uint32_t*)(out + r0 + cofs) = pack_h2(of[nt][0] * iv0, of[nt][1] * iv0);
        *(uint32_t*)(out + r1 + cofs) = pack_h2(of[nt][2] * iv1, of[nt][3] * iv1);
    }
}

// ---------------------------------------------------------------------------
// LayerNorm over D=1024; optional fused fp16 single output
// ---------------------------------------------------------------------------
__global__ __launch_bounds__(256) void layernorm_k(
    const float* __restrict__ in, const float* __restrict__ w,
    const float* __restrict__ b, float* __restrict__ out,
    __half* __restrict__ of16)
{
    __shared__ float red[8];
    __shared__ float bval;
    const int tid = threadIdx.x;
    const size_t base = (size_t)blockIdx.x * DD;

    float4 v = ((const float4*)(in + base))[tid];
    float s = v.x + v.y + v.z + v.w;
#pragma unroll
    for (int off = 16; off; off >>= 1) s += __shfl_xor_sync(0xffffffffu, s, off);
    if ((tid & 31) == 0) red[tid >> 5] = s;
    __syncthreads();
    if (tid == 0) {
        float t = 0.f;
#pragma unroll
        for (int i = 0; i < 8; ++i) t += red[i];
        bval = t * (1.0f / DD);
    }
    __syncthreads();
    const float mu = bval;
    __syncthreads();

    float dx = v.x - mu, dy = v.y - mu, dz = v.z - mu, dw = v.w - mu;
    float q = dx * dx + dy * dy + dz * dz + dw * dw;
#pragma unroll
    for (int off = 16; off; off >>= 1) q += __shfl_xor_sync(0xffffffffu, q, off);
    if ((tid & 31) == 0) red[tid >> 5] = q;
    __syncthreads();
    if (tid == 0) {
        float t = 0.f;
#pragma unroll
        for (int i = 0; i < 8; ++i) t += red[i];
        bval = t * (1.0f / DD);
    }
    __syncthreads();
    const float inv = rsqrtf(bval + 1e-5f);

    float4 w4 = ((const float4*)w)[tid];
    float4 b4 = ((const float4*)b)[tid];
    float4 r = make_float4(dx * inv * w4.x + b4.x,
                           dy * inv * w4.y + b4.y,
                           dz * inv * w4.z + b4.z,
                           dw * inv * w4.w + b4.w);
    ((float4*)(out + base))[tid] = r;
    if (of16) {
        *(uint32_t*)(of16 + base + 4 * tid)     = pack_h2(r.x, r.y);
        *(uint32_t*)(of16 + base + 4 * tid + 2) = pack_h2(r.z, r.w);
    }
}

// ---------------------------------------------------------------------------
// Launch
// ---------------------------------------------------------------------------
static inline void cvtf1(const float* in, __half* o, size_t n) {
    int n4 = (int)(n / 4);
    cvt_f16_k<<<(n4 + 255) / 256, 256>>>((const float4*)in, (uint32_t*)o, n4);
}

extern "C" void kernel_launch(void* const* d_in, const int* in_sizes, int n_in,
                              void* d_out, int out_size)
{
    const float* x     = (const float*)d_in[0];
    const float* qkv_w = (const float*)d_in[1];
    const float* qkv_b = (const float*)d_in[2];
    const float* out_w = (const float*)d_in[3];
    const float* out_b = (const float*)d_in[4];
    const float* w1    = (const float*)d_in[5];
    const float* b1    = (const float*)d_in[6];
    const float* w2    = (const float*)d_in[7];
    const float* b2    = (const float*)d_in[8];
    const float* ln1w  = (const float*)d_in[9];
    const float* ln1b  = (const float*)d_in[10];
    const float* ln2w  = (const float*)d_in[11];
    const float* ln2b  = (const float*)d_in[12];

    float* outp = (float*)d_out;
    float* kdst = outp + (size_t)MTOK * DD;
    float* vdst = outp + (size_t)2 * MTOK * DD;

    float *h1pre, *h1, *h2pre;
    __half *qkvf, *af, *h1f, *midf, *xf, *wqf, *owf, *w1f, *w2f;
    cudaGetSymbolAddress((void**)&qkvf,  g_qkvf);
    cudaGetSymbolAddress((void**)&af,    g_af);
    cudaGetSymbolAddress((void**)&h1pre, g_h1pre);
    cudaGetSymbolAddress((void**)&h1,    g_h1);
    cudaGetSymbolAddress((void**)&h2pre, g_h2pre);
    cudaGetSymbolAddress((void**)&h1f,   g_h1f);
    cudaGetSymbolAddress((void**)&midf,  g_midf);
    cudaGetSymbolAddress((void**)&xf,    g_xf);
    cudaGetSymbolAddress((void**)&wqf,   g_wqf);
    cudaGetSymbolAddress((void**)&owf,   g_owf);
    cudaGetSymbolAddress((void**)&w1f,   g_w1f);
    cudaGetSymbolAddress((void**)&w2f,   g_w2f);

    cudaFuncSetAttribute(gemm_f16_1t,
                         cudaFuncAttributeMaxDynamicSharedMemorySize, GEMM1_SMEM);
    cudaFuncSetAttribute(flash_f16_k,
                         cudaFuncAttributeMaxDynamicSharedMemorySize, FA_SMEM);

    // 0) weight / input conversions to fp16
    cvtf1(qkv_w, wqf, (size_t)3 * DD * DD);
    cvtf1(out_w, owf, (size_t)DD * DD);
    cvtf1(w1, w1f, (size_t)FF_DIM * DD);
    cvtf1(w2, w2f, (size_t)DD * FF_DIM);
    cvtf1(x,  xf,  (size_t)MTOK * DD);

    // 1) QKV projection -> qkv fp16 single; k/v fp32 to d_out
    gemm_f16_1t<<<dim3(3072 / 128, MTOK / 128), 256, GEMM1_SMEM>>>(
        xf, wqf, qkv_b, nullptr, nullptr, qkvf, kdst, vdst,
        MTOK, 3 * DD, DD, 0);
    // 2) flash attention -> attn fp16 single
    flash_f16_k<<<dim3(SS / 128, BB * HH), 256, FA_SMEM>>>(qkvf, af);
    // 3) out projection + residual x -> h1pre
    gemm_f16_1t<<<dim3(DD / 128, MTOK / 128), 256, GEMM1_SMEM>>>(
        af, owf, out_b, x, h1pre, nullptr, nullptr, nullptr,
        MTOK, DD, DD, 0);
    // 4) LN1 -> h1 fp32 + h1f fp16
    layernorm_k<<<MTOK, 256>>>(h1pre, ln1w, ln1b, h1, h1f);
    // 5) MLP up + ReLU -> midf fp16
    gemm_f16_1t<<<dim3(FF_DIM / 128, MTOK / 128), 256, GEMM1_SMEM>>>(
        h1f, w1f, b1, nullptr, nullptr, midf, nullptr, nullptr,
        MTOK, FF_DIM, DD, 1);
    // 6) MLP down + residual h1 -> h2pre fp32
    gemm_f16_1t<<<dim3(DD / 128, MTOK / 128), 256, GEMM1_SMEM>>>(
        midf, w2f, b2, h1, h2pre, nullptr, nullptr, nullptr,
        MTOK, DD, FF_DIM, 0);
    // 7) LN2 -> out
    layernorm_k<<<MTOK, 256>>>(h2pre, ln2w, ln2b, outp, nullptr);
}